// round 5
// baseline (speedup 1.0000x reference)
#include <cuda_runtime.h>
#include <cuda_bf16.h>
#include <cstdint>

#define N_NODES 50000
#define N_EDGES 800000
#define N_GRAPHS 64
#define F_IN 6
#define HID 64
#define EMB 128

// ---------------- scratch (static device globals; no allocation) ----------------
__device__ __align__(16) float g_h[(size_t)N_NODES * HID];   // pre-aggregation h = x@W
__device__ __align__(16) float g_x[(size_t)N_NODES * HID];   // post-aggregation activation
__device__ float g_dinv[N_NODES];
__device__ int   g_deg[N_NODES];
__device__ int   g_off[N_NODES];
__device__ int   g_cur[N_NODES];
__device__ int   g_chain[256];                               // chained-scan prefixes
__device__ __align__(8) int2 g_cedge[N_EDGES];               // CSR slot: {src, norm bits}
__device__ __align__(16) float g_pool[N_GRAPHS * HID];
__device__ int   g_cnt[N_GRAPHS];

__device__ __forceinline__ void red_add_v4(float* p, float4 v) {
    asm volatile("red.global.add.v4.f32 [%0], {%1,%2,%3,%4};"
                 :: "l"(p), "f"(v.x), "f"(v.y), "f"(v.z), "f"(v.w) : "memory");
}

// ---------------- setup kernels ----------------
__global__ void k_init(int n) {
    int i = blockIdx.x * blockDim.x + threadIdx.x;
    if (i < n) g_deg[i] = 0;
    if (i < N_GRAPHS * HID) g_pool[i] = 0.f;
    if (i < N_GRAPHS) g_cnt[i] = 0;
    if (i < 256) g_chain[i] = -1;
}

// degree histogram + graph-size histogram in one pass
__global__ void k_count(const int* __restrict__ dst, const int* __restrict__ batch,
                        int nE, int n) {
    int e = blockIdx.x * blockDim.x + threadIdx.x;
    if (e < nE) atomicAdd(&g_deg[dst[e]], 1);
    if (e < n)  atomicAdd(&g_cnt[batch[e]], 1);
}

// single-pass chained scan: g_off = exclusive_scan(g_deg); also g_cur, g_dinv.
// All blocks fit in one wave (196 blocks), so spinning on the previous block's
// published prefix cannot deadlock.
__global__ void k_scan(int n) {
    __shared__ int sh[256];
    __shared__ int sh_prefix;
    int i = blockIdx.x * 256 + threadIdx.x;
    int v = (i < n) ? g_deg[i] : 0;
    sh[threadIdx.x] = v;
    __syncthreads();
    #pragma unroll
    for (int off = 1; off < 256; off <<= 1) {
        int t = (threadIdx.x >= off) ? sh[threadIdx.x - off] : 0;
        __syncthreads();
        sh[threadIdx.x] += t;
        __syncthreads();
    }
    if (threadIdx.x == 255) {
        int total = sh[255];
        int prefix = 0;
        if (blockIdx.x > 0) {
            volatile int* ch = g_chain;
            int pv;
            while ((pv = ch[blockIdx.x - 1]) == -1) {}
            prefix = pv;
        }
        sh_prefix = prefix;
        __threadfence();
        atomicExch(&g_chain[blockIdx.x], prefix + total);  // publish inclusive prefix
    }
    __syncthreads();
    if (i < n) {
        int o = sh_prefix + sh[threadIdx.x] - v;   // global exclusive
        g_off[i] = o;
        g_cur[i] = o;
        g_dinv[i] = rsqrtf((float)v + 1.0f);       // +1 self-loop
    }
}

// fill CSR slots: packed {src, norm}
__global__ void k_fill(const int* __restrict__ src, const int* __restrict__ dst, int nE) {
    int e = blockIdx.x * blockDim.x + threadIdx.x;
    if (e >= nE) return;
    int s = src[e], d = dst[e];
    int pos = atomicAdd(&g_cur[d], 1);
    float nm = g_dinv[s] * g_dinv[d];
    g_cedge[pos] = make_int2(s, __float_as_int(nm));
}

// ---------------- layer 1 (fused aggregate + 6->64 gemm + bias + relu) ----------------
// block = 256 threads = 32 nodes x 8 lanes for aggregation; then 2048 outputs (32x64).
__global__ void k_layer1(const float* __restrict__ x, const float* __restrict__ W,
                         const float* __restrict__ b, int n) {
    __shared__ float Ws[F_IN][HID];     // 384 floats
    __shared__ float bs[HID];
    __shared__ float Xa[32][F_IN + 2];  // +2 pad vs bank conflicts
    int tid = threadIdx.x;
    for (int i = tid; i < F_IN * HID; i += 256) Ws[i >> 6][i & 63] = W[i];
    if (tid < HID) bs[tid] = b[tid];

    int ln = tid >> 3;                  // node lane 0..31
    int c = tid & 7;                    // feature 0..7 (6 active)
    int node = blockIdx.x * 32 + ln;
    if (node < n && c < F_IN) {
        float di = g_dinv[node];
        float acc = __ldg(x + (size_t)node * F_IN + c) * di * di;  // self-loop
        int p = g_off[node], e = p + g_deg[node];
        for (; p < e; p++) {
            int2 ed = __ldg(&g_cedge[p]);
            acc = fmaf(__ldg(x + (size_t)ed.x * F_IN + c), __int_as_float(ed.y), acc);
        }
        Xa[ln][c] = acc;
    }
    __syncthreads();

    int base = blockIdx.x * 32;
    #pragma unroll
    for (int j = 0; j < 8; j++) {
        int idx = j * 256 + tid;        // 0..2047
        int nl = idx >> 6, col = idx & 63;
        int nd = base + nl;
        if (nd < n) {
            float acc = bs[col];
            #pragma unroll
            for (int k = 0; k < F_IN; k++)
                acc = fmaf(Xa[nl][k], Ws[k][col], acc);
            g_x[(size_t)nd * HID + col] = fmaxf(acc, 0.f);
        }
    }
}

// ---------------- 64x64 gemm (register-tiled: 1 thread = 1 node x 4 cols) ----------------
__global__ void k_gemm64(const float* __restrict__ W, int n) {
    __shared__ float4 Ws[HID][HID / 4];       // 16KB
    __shared__ float Xs[16][HID + 4];
    int tid = threadIdx.x;
    const float4* W4 = reinterpret_cast<const float4*>(W);
    #pragma unroll
    for (int i = tid; i < HID * HID / 4; i += 256)
        Ws[i >> 4][i & 15] = W4[i];
    int ln = tid >> 4;
    int cg = tid & 15;
    int node = blockIdx.x * 16 + ln;
    float4 xin = (node < n)
        ? *reinterpret_cast<const float4*>(g_x + (size_t)node * HID + cg * 4)
        : make_float4(0.f, 0.f, 0.f, 0.f);
    *reinterpret_cast<float4*>(&Xs[ln][cg * 4]) = xin;
    __syncthreads();
    if (node >= n) return;
    float4 acc = make_float4(0.f, 0.f, 0.f, 0.f);
    #pragma unroll
    for (int k = 0; k < HID; k++) {
        float xv = Xs[ln][k];
        float4 w = Ws[k][cg];
        acc.x = fmaf(xv, w.x, acc.x);
        acc.y = fmaf(xv, w.y, acc.y);
        acc.z = fmaf(xv, w.z, acc.z);
        acc.w = fmaf(xv, w.w, acc.w);
    }
    *reinterpret_cast<float4*>(g_h + (size_t)node * HID + cg * 4) = acc;
}

// ---------------- aggregation (16 threads/node, float4 cols, 4x unrolled gather) ----------
template <bool POOL>
__global__ void k_agg64(const float* __restrict__ b, const int* __restrict__ batch, int n) {
    int t = blockIdx.x * blockDim.x + threadIdx.x;
    int node = t >> 4;
    if (node >= n) return;
    int c = (t & 15) << 2;
    float di = g_dinv[node];
    float sl = di * di;
    float4 acc = *reinterpret_cast<const float4*>(g_h + (size_t)node * HID + c);
    acc.x *= sl; acc.y *= sl; acc.z *= sl; acc.w *= sl;
    int p = g_off[node], e = p + g_deg[node];
    for (; p + 3 < e; p += 4) {
        int2 e0 = __ldg(&g_cedge[p]);
        int2 e1 = __ldg(&g_cedge[p + 1]);
        int2 e2 = __ldg(&g_cedge[p + 2]);
        int2 e3 = __ldg(&g_cedge[p + 3]);
        float4 v0 = *reinterpret_cast<const float4*>(g_h + (size_t)e0.x * HID + c);
        float4 v1 = *reinterpret_cast<const float4*>(g_h + (size_t)e1.x * HID + c);
        float4 v2 = *reinterpret_cast<const float4*>(g_h + (size_t)e2.x * HID + c);
        float4 v3 = *reinterpret_cast<const float4*>(g_h + (size_t)e3.x * HID + c);
        float n0 = __int_as_float(e0.y), n1 = __int_as_float(e1.y);
        float n2 = __int_as_float(e2.y), n3 = __int_as_float(e3.y);
        acc.x = fmaf(v0.x, n0, acc.x); acc.y = fmaf(v0.y, n0, acc.y);
        acc.z = fmaf(v0.z, n0, acc.z); acc.w = fmaf(v0.w, n0, acc.w);
        acc.x = fmaf(v1.x, n1, acc.x); acc.y = fmaf(v1.y, n1, acc.y);
        acc.z = fmaf(v1.z, n1, acc.z); acc.w = fmaf(v1.w, n1, acc.w);
        acc.x = fmaf(v2.x, n2, acc.x); acc.y = fmaf(v2.y, n2, acc.y);
        acc.z = fmaf(v2.z, n2, acc.z); acc.w = fmaf(v2.w, n2, acc.w);
        acc.x = fmaf(v3.x, n3, acc.x); acc.y = fmaf(v3.y, n3, acc.y);
        acc.z = fmaf(v3.z, n3, acc.z); acc.w = fmaf(v3.w, n3, acc.w);
    }
    for (; p < e; p++) {
        int2 e0 = __ldg(&g_cedge[p]);
        float4 v0 = *reinterpret_cast<const float4*>(g_h + (size_t)e0.x * HID + c);
        float n0 = __int_as_float(e0.y);
        acc.x = fmaf(v0.x, n0, acc.x); acc.y = fmaf(v0.y, n0, acc.y);
        acc.z = fmaf(v0.z, n0, acc.z); acc.w = fmaf(v0.w, n0, acc.w);
    }
    float4 bb = *reinterpret_cast<const float4*>(b + c);
    acc.x = fmaxf(acc.x + bb.x, 0.f);
    acc.y = fmaxf(acc.y + bb.y, 0.f);
    acc.z = fmaxf(acc.z + bb.z, 0.f);
    acc.w = fmaxf(acc.w + bb.w, 0.f);
    if (POOL) {
        int g = __ldg(batch + node);
        red_add_v4(g_pool + g * HID + c, acc);
    } else {
        *reinterpret_cast<float4*>(g_x + (size_t)node * HID + c) = acc;
    }
}

// ---------------- fc ----------------
__global__ void k_fc(const float* __restrict__ Wfc, const float* __restrict__ bfc,
                     float* __restrict__ out) {
    __shared__ float m[HID];
    int g = blockIdx.x;
    if (threadIdx.x < HID) {
        float c = fmaxf((float)g_cnt[g], 1.0f);
        m[threadIdx.x] = g_pool[g * HID + threadIdx.x] / c;
    }
    __syncthreads();
    int col = threadIdx.x;
    float acc = __ldg(bfc + col);
    #pragma unroll
    for (int k = 0; k < HID; k++)
        acc = fmaf(m[k], __ldg(Wfc + k * EMB + col), acc);
    out[g * EMB + col] = fmaxf(acc, 0.f);
}

// ---------------- launch ----------------
extern "C" void kernel_launch(void* const* d_in, const int* in_sizes, int n_in,
                              void* d_out, int out_size) {
    const float* x     = (const float*)d_in[0];
    const int*   ei    = (const int*)d_in[1];
    const int*   batch = (const int*)d_in[2];
    const float* W1 = (const float*)d_in[3];
    const float* b1 = (const float*)d_in[4];
    const float* W2 = (const float*)d_in[5];
    const float* b2 = (const float*)d_in[6];
    const float* W3 = (const float*)d_in[7];
    const float* b3 = (const float*)d_in[8];
    const float* Wfc = (const float*)d_in[9];
    const float* bfc = (const float*)d_in[10];
    float* out = (float*)d_out;

    const int n  = in_sizes[0] / F_IN;
    const int nE = in_sizes[1] / 2;

    const int T = 256;
    const int gN   = (n + T - 1) / T;            // 196 blocks (single wave, scan-safe)
    const int gE   = (nE + T - 1) / T;
    const int gN16 = (n * 16 + T - 1) / T;

    // setup: init, histograms, single-pass scan, CSR fill
    k_init<<<gN, T>>>(n);
    k_count<<<gE, T>>>(ei + nE, batch, nE, n);
    k_scan<<<gN, T>>>(n);
    k_fill<<<gE, T>>>(ei, ei + nE, nE);

    // layer 1 (fused)
    k_layer1<<<(n + 31) / 32, T>>>(x, W1, b1, n);

    // layer 2
    k_gemm64<<<(n + 15) / 16, T>>>(W2, n);
    k_agg64<false><<<gN16, T>>>(b2, batch, n);

    // layer 3 (aggregation fused with mean-pool reduction)
    k_gemm64<<<(n + 15) / 16, T>>>(W3, n);
    k_agg64<true><<<gN16, T>>>(b3, batch, n);

    // fc
    k_fc<<<N_GRAPHS, EMB>>>(Wfc, bfc, out);
}

// round 6
// speedup vs baseline: 1.7553x; 1.7553x over previous
#include <cuda_runtime.h>
#include <cuda_bf16.h>
#include <cstdint>

#define N_NODES 50000
#define N_EDGES 800000
#define N_GRAPHS 64
#define F_IN 6
#define HID 64
#define EMB 128

// ---------------- scratch (static device globals; no allocation) ----------------
__device__ __align__(16) float g_h[(size_t)N_NODES * HID];   // pre-aggregation h = x@W
__device__ __align__(16) float g_x[(size_t)N_NODES * HID];   // post-aggregation activation
__device__ float g_dinv[N_NODES];
__device__ int   g_deg[N_NODES];
__device__ int   g_off[N_NODES];
__device__ int   g_cur[N_NODES];
__device__ int   g_bsum[256];
__device__ __align__(8) int2 g_cedge[N_EDGES];               // CSR slot: {src, norm bits}
__device__ __align__(16) float g_pool[N_GRAPHS * HID];
__device__ int   g_cnt[N_GRAPHS];

__device__ __forceinline__ void red_add_v4(float* p, float4 v) {
    asm volatile("red.global.add.v4.f32 [%0], {%1,%2,%3,%4};"
                 :: "l"(p), "f"(v.x), "f"(v.y), "f"(v.z), "f"(v.w) : "memory");
}

// ---------------- setup kernels ----------------
__global__ void k_init(int n) {
    int i = blockIdx.x * blockDim.x + threadIdx.x;
    if (i < n) g_deg[i] = 0;
    if (i < N_GRAPHS * HID) g_pool[i] = 0.f;
    if (i < N_GRAPHS) g_cnt[i] = 0;
}

// degree histogram + graph-size histogram in one pass
__global__ void k_count(const int* __restrict__ dst, const int* __restrict__ batch,
                        int nE, int n) {
    int e = blockIdx.x * blockDim.x + threadIdx.x;
    if (e < nE) atomicAdd(&g_deg[dst[e]], 1);
    if (e < n)  atomicAdd(&g_cnt[batch[e]], 1);
}

// block-level exclusive scan of g_deg -> g_off (local), block sums -> g_bsum; also dinv
__global__ void k_scan1(int n) {
    __shared__ int sh[256];
    int i = blockIdx.x * 256 + threadIdx.x;
    int v = (i < n) ? g_deg[i] : 0;
    sh[threadIdx.x] = v;
    __syncthreads();
    #pragma unroll
    for (int off = 1; off < 256; off <<= 1) {
        int t = (threadIdx.x >= off) ? sh[threadIdx.x - off] : 0;
        __syncthreads();
        sh[threadIdx.x] += t;
        __syncthreads();
    }
    if (i < n) {
        g_off[i] = sh[threadIdx.x] - v;                  // exclusive within block
        g_dinv[i] = rsqrtf((float)v + 1.0f);             // +1 self-loop
    }
    if (threadIdx.x == 255) g_bsum[blockIdx.x] = sh[255];
}

// single-block exclusive scan of block sums (nb <= 256)
__global__ void k_scan2(int nb) {
    __shared__ int sh[256];
    int v = (threadIdx.x < nb) ? g_bsum[threadIdx.x] : 0;
    sh[threadIdx.x] = v;
    __syncthreads();
    #pragma unroll
    for (int off = 1; off < 256; off <<= 1) {
        int t = (threadIdx.x >= off) ? sh[threadIdx.x - off] : 0;
        __syncthreads();
        sh[threadIdx.x] += t;
        __syncthreads();
    }
    if (threadIdx.x < nb) g_bsum[threadIdx.x] = sh[threadIdx.x] - v;
}

__global__ void k_scan3(int n) {
    int i = blockIdx.x * 256 + threadIdx.x;
    if (i < n) {
        int o = g_off[i] + g_bsum[blockIdx.x];
        g_off[i] = o;
        g_cur[i] = o;
    }
}

// fill CSR slots: packed {src, norm}
__global__ void k_fill(const int* __restrict__ src, const int* __restrict__ dst, int nE) {
    int e = blockIdx.x * blockDim.x + threadIdx.x;
    if (e >= nE) return;
    int s = src[e], d = dst[e];
    int pos = atomicAdd(&g_cur[d], 1);
    float nm = g_dinv[s] * g_dinv[d];
    g_cedge[pos] = make_int2(s, __float_as_int(nm));
}

// ---------------- layer 1 (fused aggregate + 6->64 gemm + bias + relu) ----------------
// block = 256 threads = 32 nodes x 8 lanes for aggregation; then 2048 outputs (32x64).
__global__ void k_layer1(const float* __restrict__ x, const float* __restrict__ W,
                         const float* __restrict__ b, int n) {
    __shared__ float Ws[F_IN][HID];     // 384 floats
    __shared__ float bs[HID];
    __shared__ float Xa[32][F_IN + 2];  // +2 pad vs bank conflicts
    int tid = threadIdx.x;
    for (int i = tid; i < F_IN * HID; i += 256) Ws[i >> 6][i & 63] = W[i];
    if (tid < HID) bs[tid] = b[tid];

    int ln = tid >> 3;                  // node lane 0..31
    int c = tid & 7;                    // feature 0..7 (6 active)
    int node = blockIdx.x * 32 + ln;
    if (node < n && c < F_IN) {
        float di = g_dinv[node];
        float acc = __ldg(x + (size_t)node * F_IN + c) * di * di;  // self-loop
        int p = g_off[node], e = p + g_deg[node];
        for (; p < e; p++) {
            int2 ed = __ldg(&g_cedge[p]);
            acc = fmaf(__ldg(x + (size_t)ed.x * F_IN + c), __int_as_float(ed.y), acc);
        }
        Xa[ln][c] = acc;
    }
    __syncthreads();

    int base = blockIdx.x * 32;
    #pragma unroll
    for (int j = 0; j < 8; j++) {
        int idx = j * 256 + tid;        // 0..2047
        int nl = idx >> 6, col = idx & 63;
        int nd = base + nl;
        if (nd < n) {
            float acc = bs[col];
            #pragma unroll
            for (int k = 0; k < F_IN; k++)
                acc = fmaf(Xa[nl][k], Ws[k][col], acc);
            g_x[(size_t)nd * HID + col] = fmaxf(acc, 0.f);
        }
    }
}

// ---------------- 64x64 gemm (register-tiled: 1 thread = 1 node x 4 cols) ----------------
__global__ void k_gemm64(const float* __restrict__ W, int n) {
    __shared__ float4 Ws[HID][HID / 4];       // 16KB
    __shared__ float Xs[16][HID + 4];
    int tid = threadIdx.x;
    const float4* W4 = reinterpret_cast<const float4*>(W);
    #pragma unroll
    for (int i = tid; i < HID * HID / 4; i += 256)
        Ws[i >> 4][i & 15] = W4[i];
    int ln = tid >> 4;
    int cg = tid & 15;
    int node = blockIdx.x * 16 + ln;
    float4 xin = (node < n)
        ? *reinterpret_cast<const float4*>(g_x + (size_t)node * HID + cg * 4)
        : make_float4(0.f, 0.f, 0.f, 0.f);
    *reinterpret_cast<float4*>(&Xs[ln][cg * 4]) = xin;
    __syncthreads();
    if (node >= n) return;
    float4 acc = make_float4(0.f, 0.f, 0.f, 0.f);
    #pragma unroll
    for (int k = 0; k < HID; k++) {
        float xv = Xs[ln][k];
        float4 w = Ws[k][cg];
        acc.x = fmaf(xv, w.x, acc.x);
        acc.y = fmaf(xv, w.y, acc.y);
        acc.z = fmaf(xv, w.z, acc.z);
        acc.w = fmaf(xv, w.w, acc.w);
    }
    *reinterpret_cast<float4*>(g_h + (size_t)node * HID + cg * 4) = acc;
}

// ---------------- aggregation (16 threads/node, float4 cols, 4x unrolled gather) ----------
template <bool POOL>
__global__ void k_agg64(const float* __restrict__ b, const int* __restrict__ batch, int n) {
    int t = blockIdx.x * blockDim.x + threadIdx.x;
    int node = t >> 4;
    if (node >= n) return;
    int c = (t & 15) << 2;
    float di = g_dinv[node];
    float sl = di * di;
    float4 acc = *reinterpret_cast<const float4*>(g_h + (size_t)node * HID + c);
    acc.x *= sl; acc.y *= sl; acc.z *= sl; acc.w *= sl;
    int p = g_off[node], e = p + g_deg[node];
    for (; p + 3 < e; p += 4) {
        int2 e0 = __ldg(&g_cedge[p]);
        int2 e1 = __ldg(&g_cedge[p + 1]);
        int2 e2 = __ldg(&g_cedge[p + 2]);
        int2 e3 = __ldg(&g_cedge[p + 3]);
        float4 v0 = *reinterpret_cast<const float4*>(g_h + (size_t)e0.x * HID + c);
        float4 v1 = *reinterpret_cast<const float4*>(g_h + (size_t)e1.x * HID + c);
        float4 v2 = *reinterpret_cast<const float4*>(g_h + (size_t)e2.x * HID + c);
        float4 v3 = *reinterpret_cast<const float4*>(g_h + (size_t)e3.x * HID + c);
        float n0 = __int_as_float(e0.y), n1 = __int_as_float(e1.y);
        float n2 = __int_as_float(e2.y), n3 = __int_as_float(e3.y);
        acc.x = fmaf(v0.x, n0, acc.x); acc.y = fmaf(v0.y, n0, acc.y);
        acc.z = fmaf(v0.z, n0, acc.z); acc.w = fmaf(v0.w, n0, acc.w);
        acc.x = fmaf(v1.x, n1, acc.x); acc.y = fmaf(v1.y, n1, acc.y);
        acc.z = fmaf(v1.z, n1, acc.z); acc.w = fmaf(v1.w, n1, acc.w);
        acc.x = fmaf(v2.x, n2, acc.x); acc.y = fmaf(v2.y, n2, acc.y);
        acc.z = fmaf(v2.z, n2, acc.z); acc.w = fmaf(v2.w, n2, acc.w);
        acc.x = fmaf(v3.x, n3, acc.x); acc.y = fmaf(v3.y, n3, acc.y);
        acc.z = fmaf(v3.z, n3, acc.z); acc.w = fmaf(v3.w, n3, acc.w);
    }
    for (; p < e; p++) {
        int2 e0 = __ldg(&g_cedge[p]);
        float4 v0 = *reinterpret_cast<const float4*>(g_h + (size_t)e0.x * HID + c);
        float n0 = __int_as_float(e0.y);
        acc.x = fmaf(v0.x, n0, acc.x); acc.y = fmaf(v0.y, n0, acc.y);
        acc.z = fmaf(v0.z, n0, acc.z); acc.w = fmaf(v0.w, n0, acc.w);
    }
    float4 bb = *reinterpret_cast<const float4*>(b + c);
    acc.x = fmaxf(acc.x + bb.x, 0.f);
    acc.y = fmaxf(acc.y + bb.y, 0.f);
    acc.z = fmaxf(acc.z + bb.z, 0.f);
    acc.w = fmaxf(acc.w + bb.w, 0.f);
    if (POOL) {
        int g = __ldg(batch + node);
        red_add_v4(g_pool + g * HID + c, acc);
    } else {
        *reinterpret_cast<float4*>(g_x + (size_t)node * HID + c) = acc;
    }
}

// ---------------- fc ----------------
__global__ void k_fc(const float* __restrict__ Wfc, const float* __restrict__ bfc,
                     float* __restrict__ out) {
    __shared__ float m[HID];
    int g = blockIdx.x;
    if (threadIdx.x < HID) {
        float c = fmaxf((float)g_cnt[g], 1.0f);
        m[threadIdx.x] = g_pool[g * HID + threadIdx.x] / c;
    }
    __syncthreads();
    int col = threadIdx.x;
    float acc = __ldg(bfc + col);
    #pragma unroll
    for (int k = 0; k < HID; k++)
        acc = fmaf(m[k], __ldg(Wfc + k * EMB + col), acc);
    out[g * EMB + col] = fmaxf(acc, 0.f);
}

// ---------------- launch ----------------
extern "C" void kernel_launch(void* const* d_in, const int* in_sizes, int n_in,
                              void* d_out, int out_size) {
    const float* x     = (const float*)d_in[0];
    const int*   ei    = (const int*)d_in[1];
    const int*   batch = (const int*)d_in[2];
    const float* W1 = (const float*)d_in[3];
    const float* b1 = (const float*)d_in[4];
    const float* W2 = (const float*)d_in[5];
    const float* b2 = (const float*)d_in[6];
    const float* W3 = (const float*)d_in[7];
    const float* b3 = (const float*)d_in[8];
    const float* Wfc = (const float*)d_in[9];
    const float* bfc = (const float*)d_in[10];
    float* out = (float*)d_out;

    const int n  = in_sizes[0] / F_IN;
    const int nE = in_sizes[1] / 2;

    const int T = 256;
    const int gN   = (n + T - 1) / T;            // 196 blocks (<=256, scan-safe)
    const int gE   = (nE + T - 1) / T;
    const int gN16 = (n * 16 + T - 1) / T;

    // setup: init, histograms, 3-kernel scan (parallel, no serial chain), CSR fill
    k_init<<<gN, T>>>(n);
    k_count<<<gE, T>>>(ei + nE, batch, nE, n);
    k_scan1<<<gN, T>>>(n);
    k_scan2<<<1, T>>>(gN);
    k_scan3<<<gN, T>>>(n);
    k_fill<<<gE, T>>>(ei, ei + nE, nE);

    // layer 1 (fused)
    k_layer1<<<(n + 31) / 32, T>>>(x, W1, b1, n);

    // layer 2
    k_gemm64<<<(n + 15) / 16, T>>>(W2, n);
    k_agg64<false><<<gN16, T>>>(b2, batch, n);

    // layer 3 (aggregation fused with mean-pool reduction)
    k_gemm64<<<(n + 15) / 16, T>>>(W3, n);
    k_agg64<true><<<gN16, T>>>(b3, batch, n);

    // fc
    k_fc<<<N_GRAPHS, EMB>>>(Wfc, bfc, out);
}

// round 7
// speedup vs baseline: 1.8966x; 1.0805x over previous
#include <cuda_runtime.h>
#include <cuda_bf16.h>
#include <cstdint>

#define N_NODES 50000
#define N_EDGES 800000
#define N_GRAPHS 64
#define F_IN 6
#define HID 64
#define EMB 128

// ---------------- scratch (static device globals; no allocation) ----------------
__device__ __align__(16) float g_h[(size_t)N_NODES * HID];   // ping-pong activation buffer
__device__ __align__(16) float g_x[(size_t)N_NODES * HID];   // ping-pong activation buffer
__device__ float g_dinv[N_NODES];
__device__ int   g_deg[N_NODES];
__device__ int   g_off[N_NODES];
__device__ int   g_cur[N_NODES];
__device__ int   g_bsum[256];
__device__ __align__(8) int2 g_cedge[N_EDGES];               // CSR slot: {src, norm bits}
__device__ __align__(16) float g_pool[N_GRAPHS * HID];
__device__ int   g_cnt[N_GRAPHS];

__device__ __forceinline__ void red_add_v4(float* p, float4 v) {
    asm volatile("red.global.add.v4.f32 [%0], {%1,%2,%3,%4};"
                 :: "l"(p), "f"(v.x), "f"(v.y), "f"(v.z), "f"(v.w) : "memory");
}

// ---------------- setup kernels ----------------
__global__ void k_init(int n) {
    int i = blockIdx.x * blockDim.x + threadIdx.x;
    if (i < n) g_deg[i] = 0;
    if (i < N_GRAPHS * HID) g_pool[i] = 0.f;
    if (i < N_GRAPHS) g_cnt[i] = 0;
}

__global__ void k_count(const int* __restrict__ dst, const int* __restrict__ batch,
                        int nE, int n) {
    int e = blockIdx.x * blockDim.x + threadIdx.x;
    if (e < nE) atomicAdd(&g_deg[dst[e]], 1);
    if (e < n)  atomicAdd(&g_cnt[batch[e]], 1);
}

__global__ void k_scan1(int n) {
    __shared__ int sh[256];
    int i = blockIdx.x * 256 + threadIdx.x;
    int v = (i < n) ? g_deg[i] : 0;
    sh[threadIdx.x] = v;
    __syncthreads();
    #pragma unroll
    for (int off = 1; off < 256; off <<= 1) {
        int t = (threadIdx.x >= off) ? sh[threadIdx.x - off] : 0;
        __syncthreads();
        sh[threadIdx.x] += t;
        __syncthreads();
    }
    if (i < n) {
        g_off[i] = sh[threadIdx.x] - v;
        g_dinv[i] = rsqrtf((float)v + 1.0f);
    }
    if (threadIdx.x == 255) g_bsum[blockIdx.x] = sh[255];
}

__global__ void k_scan2(int nb) {
    __shared__ int sh[256];
    int v = (threadIdx.x < nb) ? g_bsum[threadIdx.x] : 0;
    sh[threadIdx.x] = v;
    __syncthreads();
    #pragma unroll
    for (int off = 1; off < 256; off <<= 1) {
        int t = (threadIdx.x >= off) ? sh[threadIdx.x - off] : 0;
        __syncthreads();
        sh[threadIdx.x] += t;
        __syncthreads();
    }
    if (threadIdx.x < nb) g_bsum[threadIdx.x] = sh[threadIdx.x] - v;
}

__global__ void k_scan3(int n) {
    int i = blockIdx.x * 256 + threadIdx.x;
    if (i < n) {
        int o = g_off[i] + g_bsum[blockIdx.x];
        g_off[i] = o;
        g_cur[i] = o;
    }
}

__global__ void k_fill(const int* __restrict__ src, const int* __restrict__ dst, int nE) {
    int e = blockIdx.x * blockDim.x + threadIdx.x;
    if (e >= nE) return;
    int s = src[e], d = dst[e];
    int pos = atomicAdd(&g_cur[d], 1);
    float nm = g_dinv[s] * g_dinv[d];
    g_cedge[pos] = make_int2(s, __float_as_int(nm));
}

// ---------------- layer 1 (fused aggregate + 6->64 gemm + bias + relu) ----------------
__global__ void k_layer1(const float* __restrict__ x, const float* __restrict__ W,
                         const float* __restrict__ b, int n) {
    __shared__ float Ws[F_IN][HID];
    __shared__ float bs[HID];
    __shared__ float Xa[32][F_IN + 2];
    int tid = threadIdx.x;
    for (int i = tid; i < F_IN * HID; i += 256) Ws[i >> 6][i & 63] = W[i];
    if (tid < HID) bs[tid] = b[tid];

    int ln = tid >> 3;
    int c = tid & 7;
    int node = blockIdx.x * 32 + ln;
    if (node < n && c < F_IN) {
        float di = g_dinv[node];
        float acc = __ldg(x + (size_t)node * F_IN + c) * di * di;
        int p = g_off[node], e = p + g_deg[node];
        for (; p < e; p++) {
            int2 ed = __ldg(&g_cedge[p]);
            acc = fmaf(__ldg(x + (size_t)ed.x * F_IN + c), __int_as_float(ed.y), acc);
        }
        Xa[ln][c] = acc;
    }
    __syncthreads();

    int base = blockIdx.x * 32;
    #pragma unroll
    for (int j = 0; j < 8; j++) {
        int idx = j * 256 + tid;
        int nl = idx >> 6, col = idx & 63;
        int nd = base + nl;
        if (nd < n) {
            float acc = bs[col];
            #pragma unroll
            for (int k = 0; k < F_IN; k++)
                acc = fmaf(Xa[nl][k], Ws[k][col], acc);
            g_x[(size_t)nd * HID + col] = fmaxf(acc, 0.f);
        }
    }
}

// ---------------- fused layer: out = relu((A_hat @ src) @ W + b) ----------------
// block = 256 threads, 64 nodes/block (4 groups of 16 nodes x 16 lanes).
// Phase 1: CSR gather-aggregate into shared Xs. Phase 2: 64x64 GEMM from shared.
// POOL: reduce relu'd rows into g_pool instead of writing dst.
template <bool POOL>
__global__ void k_layer64(const float* __restrict__ src, float* __restrict__ dst,
                          const float* __restrict__ W, const float* __restrict__ b,
                          const int* __restrict__ batch, int n) {
    __shared__ float4 Ws[HID][HID / 4];      // 16KB
    __shared__ float  Xs[64][HID + 4];       // 17KB (pad kills .128-store conflicts)
    __shared__ float  bs[HID];
    int tid = threadIdx.x;
    const float4* W4 = reinterpret_cast<const float4*>(W);
    #pragma unroll
    for (int i = tid; i < HID * HID / 4; i += 256)
        Ws[i >> 4][i & 15] = W4[i];
    if (tid < HID) bs[tid] = b[tid];

    int base = blockIdx.x * 64;
    int ln = tid >> 4;          // node lane 0..15
    int c4 = (tid & 15) << 2;   // col offset 0,4,...,60

    // ---- phase 1: aggregate 64 rows of src into Xs ----
    #pragma unroll
    for (int g = 0; g < 4; g++) {
        int node = base + g * 16 + ln;
        float4 acc = make_float4(0.f, 0.f, 0.f, 0.f);
        if (node < n) {
            float di = g_dinv[node];
            float sl = di * di;
            acc = *reinterpret_cast<const float4*>(src + (size_t)node * HID + c4);
            acc.x *= sl; acc.y *= sl; acc.z *= sl; acc.w *= sl;
            int p = g_off[node], e = p + g_deg[node];
            for (; p + 3 < e; p += 4) {
                int2 e0 = __ldg(&g_cedge[p]);
                int2 e1 = __ldg(&g_cedge[p + 1]);
                int2 e2 = __ldg(&g_cedge[p + 2]);
                int2 e3 = __ldg(&g_cedge[p + 3]);
                float4 v0 = *reinterpret_cast<const float4*>(src + (size_t)e0.x * HID + c4);
                float4 v1 = *reinterpret_cast<const float4*>(src + (size_t)e1.x * HID + c4);
                float4 v2 = *reinterpret_cast<const float4*>(src + (size_t)e2.x * HID + c4);
                float4 v3 = *reinterpret_cast<const float4*>(src + (size_t)e3.x * HID + c4);
                float n0 = __int_as_float(e0.y), n1 = __int_as_float(e1.y);
                float n2 = __int_as_float(e2.y), n3 = __int_as_float(e3.y);
                acc.x = fmaf(v0.x, n0, acc.x); acc.y = fmaf(v0.y, n0, acc.y);
                acc.z = fmaf(v0.z, n0, acc.z); acc.w = fmaf(v0.w, n0, acc.w);
                acc.x = fmaf(v1.x, n1, acc.x); acc.y = fmaf(v1.y, n1, acc.y);
                acc.z = fmaf(v1.z, n1, acc.z); acc.w = fmaf(v1.w, n1, acc.w);
                acc.x = fmaf(v2.x, n2, acc.x); acc.y = fmaf(v2.y, n2, acc.y);
                acc.z = fmaf(v2.z, n2, acc.z); acc.w = fmaf(v2.w, n2, acc.w);
                acc.x = fmaf(v3.x, n3, acc.x); acc.y = fmaf(v3.y, n3, acc.y);
                acc.z = fmaf(v3.z, n3, acc.z); acc.w = fmaf(v3.w, n3, acc.w);
            }
            for (; p < e; p++) {
                int2 e0 = __ldg(&g_cedge[p]);
                float4 v0 = *reinterpret_cast<const float4*>(src + (size_t)e0.x * HID + c4);
                float n0 = __int_as_float(e0.y);
                acc.x = fmaf(v0.x, n0, acc.x); acc.y = fmaf(v0.y, n0, acc.y);
                acc.z = fmaf(v0.z, n0, acc.z); acc.w = fmaf(v0.w, n0, acc.w);
            }
        }
        *reinterpret_cast<float4*>(&Xs[g * 16 + ln][c4]) = acc;
    }
    __syncthreads();

    // ---- phase 2: Y = relu(Xs @ W + b); write or pool ----
    int cg = tid & 15;
    #pragma unroll
    for (int g = 0; g < 4; g++) {
        int nl = g * 16 + ln;
        int node = base + nl;
        if (node >= n) continue;
        float4 acc = make_float4(bs[c4], bs[c4 + 1], bs[c4 + 2], bs[c4 + 3]);
        #pragma unroll
        for (int k = 0; k < HID; k++) {
            float xv = Xs[nl][k];
            float4 w = Ws[k][cg];
            acc.x = fmaf(xv, w.x, acc.x);
            acc.y = fmaf(xv, w.y, acc.y);
            acc.z = fmaf(xv, w.z, acc.z);
            acc.w = fmaf(xv, w.w, acc.w);
        }
        acc.x = fmaxf(acc.x, 0.f);
        acc.y = fmaxf(acc.y, 0.f);
        acc.z = fmaxf(acc.z, 0.f);
        acc.w = fmaxf(acc.w, 0.f);
        if (POOL) {
            int gr = __ldg(batch + node);
            red_add_v4(g_pool + gr * HID + c4, acc);
        } else {
            *reinterpret_cast<float4*>(dst + (size_t)node * HID + c4) = acc;
        }
    }
}

// ---------------- fc ----------------
__global__ void k_fc(const float* __restrict__ Wfc, const float* __restrict__ bfc,
                     float* __restrict__ out) {
    __shared__ float m[HID];
    int g = blockIdx.x;
    if (threadIdx.x < HID) {
        float c = fmaxf((float)g_cnt[g], 1.0f);
        m[threadIdx.x] = g_pool[g * HID + threadIdx.x] / c;
    }
    __syncthreads();
    int col = threadIdx.x;
    float acc = __ldg(bfc + col);
    #pragma unroll
    for (int k = 0; k < HID; k++)
        acc = fmaf(m[k], __ldg(Wfc + k * EMB + col), acc);
    out[g * EMB + col] = fmaxf(acc, 0.f);
}

// ---------------- launch ----------------
extern "C" void kernel_launch(void* const* d_in, const int* in_sizes, int n_in,
                              void* d_out, int out_size) {
    const float* x     = (const float*)d_in[0];
    const int*   ei    = (const int*)d_in[1];
    const int*   batch = (const int*)d_in[2];
    const float* W1 = (const float*)d_in[3];
    const float* b1 = (const float*)d_in[4];
    const float* W2 = (const float*)d_in[5];
    const float* b2 = (const float*)d_in[6];
    const float* W3 = (const float*)d_in[7];
    const float* b3 = (const float*)d_in[8];
    const float* Wfc = (const float*)d_in[9];
    const float* bfc = (const float*)d_in[10];
    float* out = (float*)d_out;

    const int n  = in_sizes[0] / F_IN;
    const int nE = in_sizes[1] / 2;

    const int T = 256;
    const int gN = (n + T - 1) / T;              // 196 blocks (<=256, scan-safe)
    const int gE = (nE + T - 1) / T;

    float *gx_ptr, *gh_ptr;
    cudaGetSymbolAddress((void**)&gx_ptr, g_x);
    cudaGetSymbolAddress((void**)&gh_ptr, g_h);

    // setup
    k_init<<<gN, T>>>(n);
    k_count<<<gE, T>>>(ei + nE, batch, nE, n);
    k_scan1<<<gN, T>>>(n);
    k_scan2<<<1, T>>>(gN);
    k_scan3<<<gN, T>>>(n);
    k_fill<<<gE, T>>>(ei, ei + nE, nE);

    // layer 1 (agg6 + gemm6 fused) -> g_x
    k_layer1<<<(n + 31) / 32, T>>>(x, W1, b1, n);

    // layer 2 (agg + gemm fused) g_x -> g_h
    k_layer64<false><<<(n + 63) / 64, T>>>(gx_ptr, gh_ptr, W2, b2, batch, n);

    // layer 3 (agg + gemm + mean-pool fused) g_h -> g_pool
    k_layer64<true><<<(n + 63) / 64, T>>>(gh_ptr, nullptr, W3, b3, batch, n);

    // fc
    k_fc<<<N_GRAPHS, EMB>>>(Wfc, bfc, out);
}

// round 8
// speedup vs baseline: 2.0122x; 1.0610x over previous
#include <cuda_runtime.h>
#include <cuda_fp16.h>
#include <cstdint>

#define N_NODES 50000
#define N_EDGES 800000
#define N_GRAPHS 64
#define F_IN 6
#define HID 64
#define EMB 128

// ---------------- scratch (static device globals; no allocation) ----------------
__device__ __align__(16) __half g_hx[(size_t)N_NODES * HID];  // ping-pong activation (fp16)
__device__ __align__(16) __half g_hh[(size_t)N_NODES * HID];  // ping-pong activation (fp16)
__device__ float g_dinv[N_NODES];
__device__ int   g_deg[N_NODES];
__device__ int   g_off[N_NODES];
__device__ int   g_cur[N_NODES];
__device__ int   g_total;
__device__ __align__(8) int2 g_cedge[N_EDGES];               // CSR slot: {src, norm bits}
__device__ __align__(16) float g_pool[N_GRAPHS * HID];
__device__ int   g_cnt[N_GRAPHS];

__device__ __forceinline__ void red_add_v4(float* p, float4 v) {
    asm volatile("red.global.add.v4.f32 [%0], {%1,%2,%3,%4};"
                 :: "l"(p), "f"(v.x), "f"(v.y), "f"(v.z), "f"(v.w) : "memory");
}

// ---------------- setup kernels ----------------
__global__ void k_init(int n) {
    int i = blockIdx.x * blockDim.x + threadIdx.x;
    if (i < n) g_deg[i] = 0;
    if (i < N_GRAPHS * HID) g_pool[i] = 0.f;
    if (i < N_GRAPHS) g_cnt[i] = 0;
    if (i == 0) g_total = 0;
}

__global__ void k_count(const int* __restrict__ dst, const int* __restrict__ batch,
                        int nE, int n) {
    int e = blockIdx.x * blockDim.x + threadIdx.x;
    if (e < nE) atomicAdd(&g_deg[dst[e]], 1);
    if (e < n)  atomicAdd(&g_cnt[batch[e]], 1);
}

// single-kernel offset allocation: warp-scan + one atomicAdd per warp.
// Slices are disjoint & contiguous per node (global order non-deterministic; CSR-valid).
__global__ void k_scan(int n) {
    int i = blockIdx.x * blockDim.x + threadIdx.x;
    int lane = threadIdx.x & 31;
    int v = (i < n) ? g_deg[i] : 0;
    // inclusive warp scan
    int incl = v;
    #pragma unroll
    for (int off = 1; off < 32; off <<= 1) {
        int t = __shfl_up_sync(0xffffffff, incl, off);
        if (lane >= off) incl += t;
    }
    int wtot = __shfl_sync(0xffffffff, incl, 31);
    int base = 0;
    if (lane == 31) base = atomicAdd(&g_total, wtot);
    base = __shfl_sync(0xffffffff, base, 31);
    if (i < n) {
        int o = base + incl - v;
        g_off[i] = o;
        g_cur[i] = o;
        g_dinv[i] = rsqrtf((float)v + 1.0f);   // +1 self-loop
    }
}

__global__ void k_fill(const int* __restrict__ src, const int* __restrict__ dst, int nE) {
    int e = blockIdx.x * blockDim.x + threadIdx.x;
    if (e >= nE) return;
    int s = src[e], d = dst[e];
    int pos = atomicAdd(&g_cur[d], 1);
    float nm = g_dinv[s] * g_dinv[d];
    g_cedge[pos] = make_int2(s, __float_as_int(nm));
}

// ---------------- layer 1 (fused aggregate + 6->64 gemm + bias + relu) -> fp16 ----------
__global__ void k_layer1(const float* __restrict__ x, const float* __restrict__ W,
                         const float* __restrict__ b, int n) {
    __shared__ float Ws[F_IN][HID];
    __shared__ float bs[HID];
    __shared__ float Xa[32][F_IN + 2];
    int tid = threadIdx.x;
    for (int i = tid; i < F_IN * HID; i += 256) Ws[i >> 6][i & 63] = W[i];
    if (tid < HID) bs[tid] = b[tid];

    int ln = tid >> 3;
    int c = tid & 7;
    int node = blockIdx.x * 32 + ln;
    if (node < n && c < F_IN) {
        float di = g_dinv[node];
        float acc = __ldg(x + (size_t)node * F_IN + c) * di * di;
        int p = g_off[node], e = p + g_deg[node];
        for (; p < e; p++) {
            int2 ed = __ldg(&g_cedge[p]);
            acc = fmaf(__ldg(x + (size_t)ed.x * F_IN + c), __int_as_float(ed.y), acc);
        }
        Xa[ln][c] = acc;
    }
    __syncthreads();

    int base = blockIdx.x * 32;
    #pragma unroll
    for (int j = 0; j < 8; j++) {
        int idx = j * 256 + tid;
        int nl = idx >> 6, col = idx & 63;
        int nd = base + nl;
        if (nd < n) {
            float acc = bs[col];
            #pragma unroll
            for (int k = 0; k < F_IN; k++)
                acc = fmaf(Xa[nl][k], Ws[k][col], acc);
            g_hx[(size_t)nd * HID + col] = __float2half(fmaxf(acc, 0.f));
        }
    }
}

// ---------------- fused layer: out = relu((A_hat @ src) @ W + b), fp16 I/O -------------
// block = 256 threads, 64 nodes/block (4 groups of 16 nodes x 16 lanes of 4 cols).
template <bool POOL>
__global__ void k_layer64(const __half* __restrict__ src, __half* __restrict__ dst,
                          const float* __restrict__ W, const float* __restrict__ b,
                          const int* __restrict__ batch, int n) {
    __shared__ float4 Ws[HID][HID / 4];      // 16KB
    __shared__ float  Xs[64][HID + 4];       // 17KB
    __shared__ float  bs[HID];
    int tid = threadIdx.x;
    const float4* W4 = reinterpret_cast<const float4*>(W);
    #pragma unroll
    for (int i = tid; i < HID * HID / 4; i += 256)
        Ws[i >> 4][i & 15] = W4[i];
    if (tid < HID) bs[tid] = b[tid];

    int base = blockIdx.x * 64;
    int ln = tid >> 4;            // node lane 0..15
    int lane = tid & 15;          // col-group lane
    int c4 = lane << 2;           // col offset 0,4,...,60

    // half4 loader: 4 halves = 8 bytes at row*HID + c4
    auto load4 = [&](const __half* p, int row) -> float4 {
        uint2 raw = __ldg(reinterpret_cast<const uint2*>(p + (size_t)row * HID + c4));
        __half2 ha = *reinterpret_cast<__half2*>(&raw.x);
        __half2 hb = *reinterpret_cast<__half2*>(&raw.y);
        float2 fa = __half22float2(ha);
        float2 fb = __half22float2(hb);
        return make_float4(fa.x, fa.y, fb.x, fb.y);
    };

    // ---- phase 1: aggregate 64 rows of src into Xs (fp32 accum) ----
    #pragma unroll
    for (int g = 0; g < 4; g++) {
        int node = base + g * 16 + ln;
        float4 acc = make_float4(0.f, 0.f, 0.f, 0.f);
        if (node < n) {
            float di = g_dinv[node];
            float sl = di * di;
            acc = load4(src, node);
            acc.x *= sl; acc.y *= sl; acc.z *= sl; acc.w *= sl;
            int p = g_off[node], e = p + g_deg[node];
            for (; p + 3 < e; p += 4) {
                int2 e0 = __ldg(&g_cedge[p]);
                int2 e1 = __ldg(&g_cedge[p + 1]);
                int2 e2 = __ldg(&g_cedge[p + 2]);
                int2 e3 = __ldg(&g_cedge[p + 3]);
                float4 v0 = load4(src, e0.x);
                float4 v1 = load4(src, e1.x);
                float4 v2 = load4(src, e2.x);
                float4 v3 = load4(src, e3.x);
                float n0 = __int_as_float(e0.y), n1 = __int_as_float(e1.y);
                float n2 = __int_as_float(e2.y), n3 = __int_as_float(e3.y);
                acc.x = fmaf(v0.x, n0, acc.x); acc.y = fmaf(v0.y, n0, acc.y);
                acc.z = fmaf(v0.z, n0, acc.z); acc.w = fmaf(v0.w, n0, acc.w);
                acc.x = fmaf(v1.x, n1, acc.x); acc.y = fmaf(v1.y, n1, acc.y);
                acc.z = fmaf(v1.z, n1, acc.z); acc.w = fmaf(v1.w, n1, acc.w);
                acc.x = fmaf(v2.x, n2, acc.x); acc.y = fmaf(v2.y, n2, acc.y);
                acc.z = fmaf(v2.z, n2, acc.z); acc.w = fmaf(v2.w, n2, acc.w);
                acc.x = fmaf(v3.x, n3, acc.x); acc.y = fmaf(v3.y, n3, acc.y);
                acc.z = fmaf(v3.z, n3, acc.z); acc.w = fmaf(v3.w, n3, acc.w);
            }
            for (; p < e; p++) {
                int2 e0 = __ldg(&g_cedge[p]);
                float4 v0 = load4(src, e0.x);
                float n0 = __int_as_float(e0.y);
                acc.x = fmaf(v0.x, n0, acc.x); acc.y = fmaf(v0.y, n0, acc.y);
                acc.z = fmaf(v0.z, n0, acc.z); acc.w = fmaf(v0.w, n0, acc.w);
            }
        }
        *reinterpret_cast<float4*>(&Xs[g * 16 + ln][c4]) = acc;
    }
    __syncthreads();

    // ---- phase 2: Y = relu(Xs @ W + b); write fp16 or pool fp32 ----
    #pragma unroll
    for (int g = 0; g < 4; g++) {
        int nl = g * 16 + ln;
        int node = base + nl;
        if (node >= n) continue;
        float4 acc = make_float4(bs[c4], bs[c4 + 1], bs[c4 + 2], bs[c4 + 3]);
        #pragma unroll
        for (int k = 0; k < HID; k++) {
            float xv = Xs[nl][k];
            float4 w = Ws[k][lane];
            acc.x = fmaf(xv, w.x, acc.x);
            acc.y = fmaf(xv, w.y, acc.y);
            acc.z = fmaf(xv, w.z, acc.z);
            acc.w = fmaf(xv, w.w, acc.w);
        }
        acc.x = fmaxf(acc.x, 0.f);
        acc.y = fmaxf(acc.y, 0.f);
        acc.z = fmaxf(acc.z, 0.f);
        acc.w = fmaxf(acc.w, 0.f);
        if (POOL) {
            int gr = __ldg(batch + node);
            red_add_v4(g_pool + gr * HID + c4, acc);
        } else {
            __half2 h0 = __floats2half2_rn(acc.x, acc.y);
            __half2 h1 = __floats2half2_rn(acc.z, acc.w);
            uint2 raw;
            raw.x = *reinterpret_cast<uint32_t*>(&h0);
            raw.y = *reinterpret_cast<uint32_t*>(&h1);
            *reinterpret_cast<uint2*>(dst + (size_t)node * HID + c4) = raw;
        }
    }
}

// ---------------- fc ----------------
__global__ void k_fc(const float* __restrict__ Wfc, const float* __restrict__ bfc,
                     float* __restrict__ out) {
    __shared__ float m[HID];
    int g = blockIdx.x;
    if (threadIdx.x < HID) {
        float c = fmaxf((float)g_cnt[g], 1.0f);
        m[threadIdx.x] = g_pool[g * HID + threadIdx.x] / c;
    }
    __syncthreads();
    int col = threadIdx.x;
    float acc = __ldg(bfc + col);
    #pragma unroll
    for (int k = 0; k < HID; k++)
        acc = fmaf(m[k], __ldg(Wfc + k * EMB + col), acc);
    out[g * EMB + col] = fmaxf(acc, 0.f);
}

// ---------------- launch ----------------
extern "C" void kernel_launch(void* const* d_in, const int* in_sizes, int n_in,
                              void* d_out, int out_size) {
    const float* x     = (const float*)d_in[0];
    const int*   ei    = (const int*)d_in[1];
    const int*   batch = (const int*)d_in[2];
    const float* W1 = (const float*)d_in[3];
    const float* b1 = (const float*)d_in[4];
    const float* W2 = (const float*)d_in[5];
    const float* b2 = (const float*)d_in[6];
    const float* W3 = (const float*)d_in[7];
    const float* b3 = (const float*)d_in[8];
    const float* Wfc = (const float*)d_in[9];
    const float* bfc = (const float*)d_in[10];
    float* out = (float*)d_out;

    const int n  = in_sizes[0] / F_IN;
    const int nE = in_sizes[1] / 2;

    const int T = 256;
    const int gN = (n + T - 1) / T;
    const int gE = (nE + T - 1) / T;

    __half *gx_ptr, *gh_ptr;
    cudaGetSymbolAddress((void**)&gx_ptr, g_hx);
    cudaGetSymbolAddress((void**)&gh_ptr, g_hh);

    // setup
    k_init<<<gN, T>>>(n);
    k_count<<<gE, T>>>(ei + nE, batch, nE, n);
    k_scan<<<gN, T>>>(n);
    k_fill<<<gE, T>>>(ei, ei + nE, nE);

    // layer 1 (agg6 + gemm6 fused) -> g_hx (fp16)
    k_layer1<<<(n + 31) / 32, T>>>(x, W1, b1, n);

    // layer 2 (agg + gemm fused) g_hx -> g_hh
    k_layer64<false><<<(n + 63) / 64, T>>>(gx_ptr, gh_ptr, W2, b2, batch, n);

    // layer 3 (agg + gemm + mean-pool fused) g_hh -> g_pool
    k_layer64<true><<<(n + 63) / 64, T>>>(gh_ptr, nullptr, W3, b3, batch, n);

    // fc
    k_fc<<<N_GRAPHS, EMB>>>(Wfc, bfc, out);
}

// round 9
// speedup vs baseline: 2.3870x; 1.1863x over previous
#include <cuda_runtime.h>
#include <cuda_fp16.h>
#include <cstdint>

#define N_NODES 50000
#define N_EDGES 800000
#define N_GRAPHS 64
#define F_IN 6
#define HID 64
#define EMB 128

// ---------------- scratch (static device globals; no allocation) ----------------
__device__ __align__(16) __half g_hx[(size_t)N_NODES * HID];  // ping-pong activation (fp16)
__device__ __align__(16) __half g_hh[(size_t)N_NODES * HID];  // ping-pong activation (fp16)
__device__ float g_dinv[N_NODES];
__device__ int   g_deg[N_NODES];
__device__ int   g_off[N_NODES];
__device__ int   g_cur[N_NODES];
__device__ int   g_total;
__device__ __align__(8) int2 g_cedge[N_EDGES];               // CSR slot: {src, norm bits}
__device__ __align__(16) float g_pool[N_GRAPHS * HID];
__device__ int   g_cnt[N_GRAPHS];

__device__ __forceinline__ void red_add_v4(float* p, float4 v) {
    asm volatile("red.global.add.v4.f32 [%0], {%1,%2,%3,%4};"
                 :: "l"(p), "f"(v.x), "f"(v.y), "f"(v.z), "f"(v.w) : "memory");
}

// ---------------- setup kernels ----------------
__global__ void k_init(int n) {
    int i = blockIdx.x * blockDim.x + threadIdx.x;
    if (i < n) g_deg[i] = 0;
    if (i < N_GRAPHS * HID) g_pool[i] = 0.f;
    if (i < N_GRAPHS) g_cnt[i] = 0;
    if (i == 0) g_total = 0;
}

__global__ void k_count(const int* __restrict__ dst, const int* __restrict__ batch,
                        int nE, int n) {
    int e = blockIdx.x * blockDim.x + threadIdx.x;
    if (e < nE) atomicAdd(&g_deg[dst[e]], 1);
    if (e < n)  atomicAdd(&g_cnt[batch[e]], 1);
}

// single-kernel offset allocation: warp-scan + one atomicAdd per warp.
__global__ void k_scan(int n) {
    int i = blockIdx.x * blockDim.x + threadIdx.x;
    int lane = threadIdx.x & 31;
    int v = (i < n) ? g_deg[i] : 0;
    int incl = v;
    #pragma unroll
    for (int off = 1; off < 32; off <<= 1) {
        int t = __shfl_up_sync(0xffffffff, incl, off);
        if (lane >= off) incl += t;
    }
    int wtot = __shfl_sync(0xffffffff, incl, 31);
    int base = 0;
    if (lane == 31) base = atomicAdd(&g_total, wtot);
    base = __shfl_sync(0xffffffff, base, 31);
    if (i < n) {
        int o = base + incl - v;
        g_off[i] = o;
        g_cur[i] = o;
        g_dinv[i] = rsqrtf((float)v + 1.0f);   // +1 self-loop
    }
}

// fill CSR slots, 2 edges/thread for MLP
__global__ void k_fill(const int* __restrict__ src, const int* __restrict__ dst, int nE) {
    int t = blockIdx.x * blockDim.x + threadIdx.x;
    int e0 = t * 2;
    if (e0 >= nE) return;
    int s0 = __ldg(src + e0), d0 = __ldg(dst + e0);
    int have1 = (e0 + 1 < nE);
    int s1 = have1 ? __ldg(src + e0 + 1) : 0;
    int d1 = have1 ? __ldg(dst + e0 + 1) : 0;
    float nm0 = g_dinv[s0] * g_dinv[d0];
    int p0 = atomicAdd(&g_cur[d0], 1);
    g_cedge[p0] = make_int2(s0, __float_as_int(nm0));
    if (have1) {
        float nm1 = g_dinv[s1] * g_dinv[d1];
        int p1 = atomicAdd(&g_cur[d1], 1);
        g_cedge[p1] = make_int2(s1, __float_as_int(nm1));
    }
}

// ---------------- layer 1 (fused aggregate + 6->64 gemm + bias + relu) -> fp16 ----------
__global__ void k_layer1(const float* __restrict__ x, const float* __restrict__ W,
                         const float* __restrict__ b, int n) {
    __shared__ float Ws[F_IN][HID];
    __shared__ float bs[HID];
    __shared__ float Xa[32][F_IN + 2];
    int tid = threadIdx.x;
    for (int i = tid; i < F_IN * HID; i += 256) Ws[i >> 6][i & 63] = W[i];
    if (tid < HID) bs[tid] = b[tid];

    int ln = tid >> 3;
    int c = tid & 7;
    int node = blockIdx.x * 32 + ln;
    if (node < n && c < F_IN) {
        float di = g_dinv[node];
        float acc = __ldg(x + (size_t)node * F_IN + c) * di * di;
        int p = g_off[node], e = p + g_deg[node];
        for (; p < e; p++) {
            int2 ed = __ldg(&g_cedge[p]);
            acc = fmaf(__ldg(x + (size_t)ed.x * F_IN + c), __int_as_float(ed.y), acc);
        }
        Xa[ln][c] = acc;
    }
    __syncthreads();

    int base = blockIdx.x * 32;
    #pragma unroll
    for (int j = 0; j < 8; j++) {
        int idx = j * 256 + tid;
        int nl = idx >> 6, col = idx & 63;
        int nd = base + nl;
        if (nd < n) {
            float acc = bs[col];
            #pragma unroll
            for (int k = 0; k < F_IN; k++)
                acc = fmaf(Xa[nl][k], Ws[k][col], acc);
            g_hx[(size_t)nd * HID + col] = __float2half(fmaxf(acc, 0.f));
        }
    }
}

// ---------------- fused layer: out = relu((A_hat @ src) @ W + b), fp16 I/O -------------
// 256 threads, 64 nodes/block.
// Phase 1: gather-aggregate (16 lanes x 4 cols per node), store TRANSPOSED Xs_T[k][node].
// Phase 2: 4x4 register tile per thread: 2x LDS.128 -> 16 FMA per k.
template <bool POOL>
__global__ void k_layer64(const __half* __restrict__ src, __half* __restrict__ dst,
                          const float* __restrict__ W, const float* __restrict__ b,
                          const int* __restrict__ batch, int n) {
    __shared__ float4 Ws[HID][HID / 4];      // 16KB  [k][colgroup]
    __shared__ float  XsT[HID][64 + 4];      // 17KB  [k][node_local], row=68 floats (f4-aligned)
    __shared__ float  bs[HID];
    int tid = threadIdx.x;
    const float4* W4 = reinterpret_cast<const float4*>(W);
    #pragma unroll
    for (int i = tid; i < HID * HID / 4; i += 256)
        Ws[i >> 4][i & 15] = W4[i];
    if (tid < HID) bs[tid] = b[tid];

    int base = blockIdx.x * 64;
    int ln = tid >> 4;            // node lane 0..15
    int lane = tid & 15;          // col-group lane
    int c4 = lane << 2;           // col offset 0,4,...,60

    auto load4 = [&](const __half* p, int row) -> float4 {
        uint2 raw = __ldg(reinterpret_cast<const uint2*>(p + (size_t)row * HID + c4));
        __half2 ha = *reinterpret_cast<__half2*>(&raw.x);
        __half2 hb = *reinterpret_cast<__half2*>(&raw.y);
        float2 fa = __half22float2(ha);
        float2 fb = __half22float2(hb);
        return make_float4(fa.x, fa.y, fb.x, fb.y);
    };

    // ---- phase 1: aggregate 64 rows; store transposed into XsT ----
    #pragma unroll
    for (int g = 0; g < 4; g++) {
        int nl = g * 16 + ln;
        int node = base + nl;
        float4 acc = make_float4(0.f, 0.f, 0.f, 0.f);
        if (node < n) {
            float di = g_dinv[node];
            float sl = di * di;
            acc = load4(src, node);
            acc.x *= sl; acc.y *= sl; acc.z *= sl; acc.w *= sl;
            int p = g_off[node], e = p + g_deg[node];
            for (; p + 3 < e; p += 4) {
                int2 e0 = __ldg(&g_cedge[p]);
                int2 e1 = __ldg(&g_cedge[p + 1]);
                int2 e2 = __ldg(&g_cedge[p + 2]);
                int2 e3 = __ldg(&g_cedge[p + 3]);
                float4 v0 = load4(src, e0.x);
                float4 v1 = load4(src, e1.x);
                float4 v2 = load4(src, e2.x);
                float4 v3 = load4(src, e3.x);
                float n0 = __int_as_float(e0.y), n1 = __int_as_float(e1.y);
                float n2 = __int_as_float(e2.y), n3 = __int_as_float(e3.y);
                acc.x = fmaf(v0.x, n0, acc.x); acc.y = fmaf(v0.y, n0, acc.y);
                acc.z = fmaf(v0.z, n0, acc.z); acc.w = fmaf(v0.w, n0, acc.w);
                acc.x = fmaf(v1.x, n1, acc.x); acc.y = fmaf(v1.y, n1, acc.y);
                acc.z = fmaf(v1.z, n1, acc.z); acc.w = fmaf(v1.w, n1, acc.w);
                acc.x = fmaf(v2.x, n2, acc.x); acc.y = fmaf(v2.y, n2, acc.y);
                acc.z = fmaf(v2.z, n2, acc.z); acc.w = fmaf(v2.w, n2, acc.w);
                acc.x = fmaf(v3.x, n3, acc.x); acc.y = fmaf(v3.y, n3, acc.y);
                acc.z = fmaf(v3.z, n3, acc.z); acc.w = fmaf(v3.w, n3, acc.w);
            }
            for (; p < e; p++) {
                int2 e0 = __ldg(&g_cedge[p]);
                float4 v0 = load4(src, e0.x);
                float n0 = __int_as_float(e0.y);
                acc.x = fmaf(v0.x, n0, acc.x); acc.y = fmaf(v0.y, n0, acc.y);
                acc.z = fmaf(v0.z, n0, acc.z); acc.w = fmaf(v0.w, n0, acc.w);
            }
        }
        XsT[c4 + 0][nl] = acc.x;
        XsT[c4 + 1][nl] = acc.y;
        XsT[c4 + 2][nl] = acc.z;
        XsT[c4 + 3][nl] = acc.w;
    }
    __syncthreads();

    // ---- phase 2: 4x4 register tile; Y = relu(X @ W + b) ----
    int ng = tid >> 4;            // node group 0..15 (4 nodes)
    // lane = col group 0..15 (4 cols), c4 as above
    float4 bb = make_float4(bs[c4], bs[c4 + 1], bs[c4 + 2], bs[c4 + 3]);
    float4 a0 = bb, a1 = bb, a2 = bb, a3 = bb;
    #pragma unroll
    for (int k = 0; k < HID; k++) {
        float4 xv = *reinterpret_cast<const float4*>(&XsT[k][ng * 4]);
        float4 w  = Ws[k][lane];
        a0.x = fmaf(xv.x, w.x, a0.x); a0.y = fmaf(xv.x, w.y, a0.y);
        a0.z = fmaf(xv.x, w.z, a0.z); a0.w = fmaf(xv.x, w.w, a0.w);
        a1.x = fmaf(xv.y, w.x, a1.x); a1.y = fmaf(xv.y, w.y, a1.y);
        a1.z = fmaf(xv.y, w.z, a1.z); a1.w = fmaf(xv.y, w.w, a1.w);
        a2.x = fmaf(xv.z, w.x, a2.x); a2.y = fmaf(xv.z, w.y, a2.y);
        a2.z = fmaf(xv.z, w.z, a2.z); a2.w = fmaf(xv.z, w.w, a2.w);
        a3.x = fmaf(xv.w, w.x, a3.x); a3.y = fmaf(xv.w, w.y, a3.y);
        a3.z = fmaf(xv.w, w.z, a3.z); a3.w = fmaf(xv.w, w.w, a3.w);
    }
    float4 accs[4] = {a0, a1, a2, a3};
    #pragma unroll
    for (int i = 0; i < 4; i++) {
        int node = base + ng * 4 + i;
        if (node >= n) continue;
        float4 acc = accs[i];
        acc.x = fmaxf(acc.x, 0.f);
        acc.y = fmaxf(acc.y, 0.f);
        acc.z = fmaxf(acc.z, 0.f);
        acc.w = fmaxf(acc.w, 0.f);
        if (POOL) {
            int gr = __ldg(batch + node);
            red_add_v4(g_pool + gr * HID + c4, acc);
        } else {
            __half2 h0 = __floats2half2_rn(acc.x, acc.y);
            __half2 h1 = __floats2half2_rn(acc.z, acc.w);
            uint2 raw;
            raw.x = *reinterpret_cast<uint32_t*>(&h0);
            raw.y = *reinterpret_cast<uint32_t*>(&h1);
            *reinterpret_cast<uint2*>(dst + (size_t)node * HID + c4) = raw;
        }
    }
}

// ---------------- fc ----------------
__global__ void k_fc(const float* __restrict__ Wfc, const float* __restrict__ bfc,
                     float* __restrict__ out) {
    __shared__ float m[HID];
    int g = blockIdx.x;
    if (threadIdx.x < HID) {
        float c = fmaxf((float)g_cnt[g], 1.0f);
        m[threadIdx.x] = g_pool[g * HID + threadIdx.x] / c;
    }
    __syncthreads();
    int col = threadIdx.x;
    float acc = __ldg(bfc + col);
    #pragma unroll
    for (int k = 0; k < HID; k++)
        acc = fmaf(m[k], __ldg(Wfc + k * EMB + col), acc);
    out[g * EMB + col] = fmaxf(acc, 0.f);
}

// ---------------- launch ----------------
extern "C" void kernel_launch(void* const* d_in, const int* in_sizes, int n_in,
                              void* d_out, int out_size) {
    const float* x     = (const float*)d_in[0];
    const int*   ei    = (const int*)d_in[1];
    const int*   batch = (const int*)d_in[2];
    const float* W1 = (const float*)d_in[3];
    const float* b1 = (const float*)d_in[4];
    const float* W2 = (const float*)d_in[5];
    const float* b2 = (const float*)d_in[6];
    const float* W3 = (const float*)d_in[7];
    const float* b3 = (const float*)d_in[8];
    const float* Wfc = (const float*)d_in[9];
    const float* bfc = (const float*)d_in[10];
    float* out = (float*)d_out;

    const int n  = in_sizes[0] / F_IN;
    const int nE = in_sizes[1] / 2;

    const int T = 256;
    const int gN = (n + T - 1) / T;
    const int gE = (nE + T - 1) / T;
    const int gE2 = (nE / 2 + T - 1) / T;

    __half *gx_ptr, *gh_ptr;
    cudaGetSymbolAddress((void**)&gx_ptr, g_hx);
    cudaGetSymbolAddress((void**)&gh_ptr, g_hh);

    // setup
    k_init<<<gN, T>>>(n);
    k_count<<<gE, T>>>(ei + nE, batch, nE, n);
    k_scan<<<gN, T>>>(n);
    k_fill<<<gE2, T>>>(ei, ei + nE, nE);

    // layer 1 (agg6 + gemm6 fused) -> g_hx (fp16)
    k_layer1<<<(n + 31) / 32, T>>>(x, W1, b1, n);

    // layer 2 (agg + gemm fused) g_hx -> g_hh
    k_layer64<false><<<(n + 63) / 64, T>>>(gx_ptr, gh_ptr, W2, b2, batch, n);

    // layer 3 (agg + gemm + mean-pool fused) g_hh -> g_pool
    k_layer64<true><<<(n + 63) / 64, T>>>(gh_ptr, nullptr, W3, b3, batch, n);

    // fc
    k_fc<<<N_GRAPHS, EMB>>>(Wfc, bfc, out);
}

// round 10
// speedup vs baseline: 2.8266x; 1.1842x over previous
#include <cuda_runtime.h>
#include <cuda_fp16.h>
#include <cstdint>

#define N_NODES 50000
#define N_EDGES 800000
#define N_GRAPHS 64
#define F_IN 6
#define HID 64
#define EMB 128

// ---------------- scratch (static device globals; no allocation) ----------------
__device__ __align__(16) __half g_hx[(size_t)N_NODES * HID];  // ping-pong activation (fp16)
__device__ __align__(16) __half g_hh[(size_t)N_NODES * HID];  // ping-pong activation (fp16)
__device__ float g_dinv[N_NODES];
__device__ int   g_deg[N_NODES];
__device__ int   g_off[N_NODES];
__device__ int   g_cur[N_NODES];
__device__ int   g_total;
__device__ __align__(8) int2 g_cedge[N_EDGES];               // CSR slot: {src, norm bits}
__device__ __align__(16) float g_pool[N_GRAPHS * HID];

__device__ __forceinline__ void red_add_v4(float* p, float4 v) {
    asm volatile("red.global.add.v4.f32 [%0], {%1,%2,%3,%4};"
                 :: "l"(p), "f"(v.x), "f"(v.y), "f"(v.z), "f"(v.w) : "memory");
}

// ---------------- setup kernels ----------------
__global__ void k_init(int n) {
    int i = blockIdx.x * blockDim.x + threadIdx.x;
    if (i < n) g_deg[i] = 0;
    if (i < N_GRAPHS * HID) g_pool[i] = 0.f;
    if (i == 0) g_total = 0;
}

// degree histogram: 4 edges/thread, int4 loads, 4 atomics in flight
__global__ void k_count(const int* __restrict__ dst, int nE) {
    int t = blockIdx.x * blockDim.x + threadIdx.x;
    int e = t << 2;
    if (e + 3 < nE) {
        int4 d = __ldg(reinterpret_cast<const int4*>(dst + e));
        atomicAdd(&g_deg[d.x], 1);
        atomicAdd(&g_deg[d.y], 1);
        atomicAdd(&g_deg[d.z], 1);
        atomicAdd(&g_deg[d.w], 1);
    } else {
        for (int i = e; i < nE; i++) atomicAdd(&g_deg[__ldg(dst + i)], 1);
    }
}

// single-kernel offset allocation: warp-scan + one atomicAdd per warp.
__global__ void k_scan(int n) {
    int i = blockIdx.x * blockDim.x + threadIdx.x;
    int lane = threadIdx.x & 31;
    int v = (i < n) ? g_deg[i] : 0;
    int incl = v;
    #pragma unroll
    for (int off = 1; off < 32; off <<= 1) {
        int t = __shfl_up_sync(0xffffffff, incl, off);
        if (lane >= off) incl += t;
    }
    int wtot = __shfl_sync(0xffffffff, incl, 31);
    int base = 0;
    if (lane == 31) base = atomicAdd(&g_total, wtot);
    base = __shfl_sync(0xffffffff, base, 31);
    if (i < n) {
        int o = base + incl - v;
        g_off[i] = o;
        g_cur[i] = o;
        g_dinv[i] = rsqrtf((float)v + 1.0f);   // +1 self-loop
    }
}

// fill CSR slots: 4 edges/thread, batched loads, 4 cursor-atomics in flight
__global__ void k_fill(const int* __restrict__ src, const int* __restrict__ dst, int nE) {
    int t = blockIdx.x * blockDim.x + threadIdx.x;
    int e = t << 2;
    if (e + 3 < nE) {
        int4 s = __ldg(reinterpret_cast<const int4*>(src + e));
        int4 d = __ldg(reinterpret_cast<const int4*>(dst + e));
        float ds0 = g_dinv[s.x], ds1 = g_dinv[s.y], ds2 = g_dinv[s.z], ds3 = g_dinv[s.w];
        float dd0 = g_dinv[d.x], dd1 = g_dinv[d.y], dd2 = g_dinv[d.z], dd3 = g_dinv[d.w];
        int p0 = atomicAdd(&g_cur[d.x], 1);
        int p1 = atomicAdd(&g_cur[d.y], 1);
        int p2 = atomicAdd(&g_cur[d.z], 1);
        int p3 = atomicAdd(&g_cur[d.w], 1);
        g_cedge[p0] = make_int2(s.x, __float_as_int(ds0 * dd0));
        g_cedge[p1] = make_int2(s.y, __float_as_int(ds1 * dd1));
        g_cedge[p2] = make_int2(s.z, __float_as_int(ds2 * dd2));
        g_cedge[p3] = make_int2(s.w, __float_as_int(ds3 * dd3));
    } else {
        for (int i = e; i < nE; i++) {
            int s = __ldg(src + i), d = __ldg(dst + i);
            int p = atomicAdd(&g_cur[d], 1);
            g_cedge[p] = make_int2(s, __float_as_int(g_dinv[s] * g_dinv[d]));
        }
    }
}

// ---------------- layer 1 (fused aggregate + 6->64 gemm + bias + relu) -> fp16 ----------
__global__ void k_layer1(const float* __restrict__ x, const float* __restrict__ W,
                         const float* __restrict__ b, int n) {
    __shared__ float Ws[F_IN][HID];
    __shared__ float bs[HID];
    __shared__ float Xa[32][F_IN + 2];
    int tid = threadIdx.x;
    for (int i = tid; i < F_IN * HID; i += 256) Ws[i >> 6][i & 63] = W[i];
    if (tid < HID) bs[tid] = b[tid];

    int ln = tid >> 3;
    int c = tid & 7;
    int node = blockIdx.x * 32 + ln;
    if (node < n && c < F_IN) {
        float di = g_dinv[node];
        float acc = __ldg(x + (size_t)node * F_IN + c) * di * di;
        int p = g_off[node], e = p + g_deg[node];
        for (; p < e; p++) {
            int2 ed = __ldg(&g_cedge[p]);
            acc = fmaf(__ldg(x + (size_t)ed.x * F_IN + c), __int_as_float(ed.y), acc);
        }
        Xa[ln][c] = acc;
    }
    __syncthreads();

    int base = blockIdx.x * 32;
    #pragma unroll
    for (int j = 0; j < 8; j++) {
        int idx = j * 256 + tid;
        int nl = idx >> 6, col = idx & 63;
        int nd = base + nl;
        if (nd < n) {
            float acc = bs[col];
            #pragma unroll
            for (int k = 0; k < F_IN; k++)
                acc = fmaf(Xa[nl][k], Ws[k][col], acc);
            g_hx[(size_t)nd * HID + col] = __float2half(fmaxf(acc, 0.f));
        }
    }
}

// ---------------- fused layer: out = relu((A_hat @ src) @ W + b), fp16 I/O -------------
template <bool POOL>
__global__ void k_layer64(const __half* __restrict__ src, __half* __restrict__ dst,
                          const float* __restrict__ W, const float* __restrict__ b,
                          const int* __restrict__ batch, int n) {
    __shared__ float4 Ws[HID][HID / 4];      // 16KB  [k][colgroup]
    __shared__ float  XsT[HID][64 + 4];      // 17KB  [k][node_local]
    __shared__ float  bs[HID];
    int tid = threadIdx.x;
    const float4* W4 = reinterpret_cast<const float4*>(W);
    #pragma unroll
    for (int i = tid; i < HID * HID / 4; i += 256)
        Ws[i >> 4][i & 15] = W4[i];
    if (tid < HID) bs[tid] = b[tid];

    int base = blockIdx.x * 64;
    int ln = tid >> 4;            // node lane 0..15
    int lane = tid & 15;          // col-group lane
    int c4 = lane << 2;

    auto load4 = [&](const __half* p, int row) -> float4 {
        uint2 raw = __ldg(reinterpret_cast<const uint2*>(p + (size_t)row * HID + c4));
        __half2 ha = *reinterpret_cast<__half2*>(&raw.x);
        __half2 hb = *reinterpret_cast<__half2*>(&raw.y);
        float2 fa = __half22float2(ha);
        float2 fb = __half22float2(hb);
        return make_float4(fa.x, fa.y, fb.x, fb.y);
    };

    // ---- phase 1: aggregate 64 rows; store transposed into XsT ----
    #pragma unroll
    for (int g = 0; g < 4; g++) {
        int nl = g * 16 + ln;
        int node = base + nl;
        float4 acc = make_float4(0.f, 0.f, 0.f, 0.f);
        if (node < n) {
            float di = g_dinv[node];
            float sl = di * di;
            acc = load4(src, node);
            acc.x *= sl; acc.y *= sl; acc.z *= sl; acc.w *= sl;
            int p = g_off[node], e = p + g_deg[node];
            for (; p + 3 < e; p += 4) {
                int2 e0 = __ldg(&g_cedge[p]);
                int2 e1 = __ldg(&g_cedge[p + 1]);
                int2 e2 = __ldg(&g_cedge[p + 2]);
                int2 e3 = __ldg(&g_cedge[p + 3]);
                float4 v0 = load4(src, e0.x);
                float4 v1 = load4(src, e1.x);
                float4 v2 = load4(src, e2.x);
                float4 v3 = load4(src, e3.x);
                float n0 = __int_as_float(e0.y), n1 = __int_as_float(e1.y);
                float n2 = __int_as_float(e2.y), n3 = __int_as_float(e3.y);
                acc.x = fmaf(v0.x, n0, acc.x); acc.y = fmaf(v0.y, n0, acc.y);
                acc.z = fmaf(v0.z, n0, acc.z); acc.w = fmaf(v0.w, n0, acc.w);
                acc.x = fmaf(v1.x, n1, acc.x); acc.y = fmaf(v1.y, n1, acc.y);
                acc.z = fmaf(v1.z, n1, acc.z); acc.w = fmaf(v1.w, n1, acc.w);
                acc.x = fmaf(v2.x, n2, acc.x); acc.y = fmaf(v2.y, n2, acc.y);
                acc.z = fmaf(v2.z, n2, acc.z); acc.w = fmaf(v2.w, n2, acc.w);
                acc.x = fmaf(v3.x, n3, acc.x); acc.y = fmaf(v3.y, n3, acc.y);
                acc.z = fmaf(v3.z, n3, acc.z); acc.w = fmaf(v3.w, n3, acc.w);
            }
            for (; p < e; p++) {
                int2 e0 = __ldg(&g_cedge[p]);
                float4 v0 = load4(src, e0.x);
                float n0 = __int_as_float(e0.y);
                acc.x = fmaf(v0.x, n0, acc.x); acc.y = fmaf(v0.y, n0, acc.y);
                acc.z = fmaf(v0.z, n0, acc.z); acc.w = fmaf(v0.w, n0, acc.w);
            }
        }
        XsT[c4 + 0][nl] = acc.x;
        XsT[c4 + 1][nl] = acc.y;
        XsT[c4 + 2][nl] = acc.z;
        XsT[c4 + 3][nl] = acc.w;
    }
    __syncthreads();

    // ---- phase 2: 4x4 register tile; Y = relu(X @ W + b) ----
    int ng = tid >> 4;
    float4 bb = make_float4(bs[c4], bs[c4 + 1], bs[c4 + 2], bs[c4 + 3]);
    float4 a0 = bb, a1 = bb, a2 = bb, a3 = bb;
    #pragma unroll
    for (int k = 0; k < HID; k++) {
        float4 xv = *reinterpret_cast<const float4*>(&XsT[k][ng * 4]);
        float4 w  = Ws[k][lane];
        a0.x = fmaf(xv.x, w.x, a0.x); a0.y = fmaf(xv.x, w.y, a0.y);
        a0.z = fmaf(xv.x, w.z, a0.z); a0.w = fmaf(xv.x, w.w, a0.w);
        a1.x = fmaf(xv.y, w.x, a1.x); a1.y = fmaf(xv.y, w.y, a1.y);
        a1.z = fmaf(xv.y, w.z, a1.z); a1.w = fmaf(xv.y, w.w, a1.w);
        a2.x = fmaf(xv.z, w.x, a2.x); a2.y = fmaf(xv.z, w.y, a2.y);
        a2.z = fmaf(xv.z, w.z, a2.z); a2.w = fmaf(xv.z, w.w, a2.w);
        a3.x = fmaf(xv.w, w.x, a3.x); a3.y = fmaf(xv.w, w.y, a3.y);
        a3.z = fmaf(xv.w, w.z, a3.z); a3.w = fmaf(xv.w, w.w, a3.w);
    }
    float4 accs[4] = {a0, a1, a2, a3};
    #pragma unroll
    for (int i = 0; i < 4; i++) {
        int node = base + ng * 4 + i;
        if (node >= n) continue;
        float4 acc = accs[i];
        acc.x = fmaxf(acc.x, 0.f);
        acc.y = fmaxf(acc.y, 0.f);
        acc.z = fmaxf(acc.z, 0.f);
        acc.w = fmaxf(acc.w, 0.f);
        if (POOL) {
            int gr = __ldg(batch + node);
            red_add_v4(g_pool + gr * HID + c4, acc);
        } else {
            __half2 h0 = __floats2half2_rn(acc.x, acc.y);
            __half2 h1 = __floats2half2_rn(acc.z, acc.w);
            uint2 raw;
            raw.x = *reinterpret_cast<uint32_t*>(&h0);
            raw.y = *reinterpret_cast<uint32_t*>(&h1);
            *reinterpret_cast<uint2*>(dst + (size_t)node * HID + c4) = raw;
        }
    }
}

// ---------------- fc (graph sizes via binary search on sorted batch) ----------------
__global__ void k_fc(const float* __restrict__ Wfc, const float* __restrict__ bfc,
                     const int* __restrict__ batch, int n, float* __restrict__ out) {
    __shared__ float m[HID];
    __shared__ float inv_cnt;
    int g = blockIdx.x;
    if (threadIdx.x == 0) {
        // lower bound of g and of g+1 in sorted batch
        int lo = 0, hi = n;
        while (lo < hi) { int mid = (lo + hi) >> 1; if (__ldg(batch + mid) < g) lo = mid + 1; else hi = mid; }
        int start = lo;
        lo = start; hi = n;
        while (lo < hi) { int mid = (lo + hi) >> 1; if (__ldg(batch + mid) < g + 1) lo = mid + 1; else hi = mid; }
        int cnt = lo - start;
        inv_cnt = 1.0f / fmaxf((float)cnt, 1.0f);
    }
    __syncthreads();
    if (threadIdx.x < HID) {
        m[threadIdx.x] = g_pool[g * HID + threadIdx.x] * inv_cnt;
    }
    __syncthreads();
    int col = threadIdx.x;
    float acc = __ldg(bfc + col);
    #pragma unroll
    for (int k = 0; k < HID; k++)
        acc = fmaf(m[k], __ldg(Wfc + k * EMB + col), acc);
    out[g * EMB + col] = fmaxf(acc, 0.f);
}

// ---------------- launch ----------------
extern "C" void kernel_launch(void* const* d_in, const int* in_sizes, int n_in,
                              void* d_out, int out_size) {
    const float* x     = (const float*)d_in[0];
    const int*   ei    = (const int*)d_in[1];
    const int*   batch = (const int*)d_in[2];
    const float* W1 = (const float*)d_in[3];
    const float* b1 = (const float*)d_in[4];
    const float* W2 = (const float*)d_in[5];
    const float* b2 = (const float*)d_in[6];
    const float* W3 = (const float*)d_in[7];
    const float* b3 = (const float*)d_in[8];
    const float* Wfc = (const float*)d_in[9];
    const float* bfc = (const float*)d_in[10];
    float* out = (float*)d_out;

    const int n  = in_sizes[0] / F_IN;
    const int nE = in_sizes[1] / 2;

    const int T = 256;
    const int gN  = (n + T - 1) / T;
    const int gE4 = ((nE + 3) / 4 + T - 1) / T;

    __half *gx_ptr, *gh_ptr;
    cudaGetSymbolAddress((void**)&gx_ptr, g_hx);
    cudaGetSymbolAddress((void**)&gh_ptr, g_hh);

    // setup
    k_init<<<gN, T>>>(n);
    k_count<<<gE4, T>>>(ei + nE, nE);
    k_scan<<<gN, T>>>(n);
    k_fill<<<gE4, T>>>(ei, ei + nE, nE);

    // layer 1 (agg6 + gemm6 fused) -> g_hx (fp16)
    k_layer1<<<(n + 31) / 32, T>>>(x, W1, b1, n);

    // layer 2 (agg + gemm fused) g_hx -> g_hh
    k_layer64<false><<<(n + 63) / 64, T>>>(gx_ptr, gh_ptr, W2, b2, batch, n);

    // layer 3 (agg + gemm + mean-pool fused) g_hh -> g_pool
    k_layer64<true><<<(n + 63) / 64, T>>>(gh_ptr, nullptr, W3, b3, batch, n);

    // fc
    k_fc<<<N_GRAPHS, EMB>>>(Wfc, bfc, batch, n, out);
}

// round 11
// speedup vs baseline: 2.8456x; 1.0067x over previous
#include <cuda_runtime.h>
#include <cuda_fp16.h>
#include <cstdint>

#define N_NODES 50000
#define N_EDGES 800000
#define N_GRAPHS 64
#define F_IN 6
#define HID 64
#define EMB 128

// ---------------- scratch (static device globals; no allocation) ----------------
__device__ __align__(16) __half g_hx[(size_t)N_NODES * HID];  // ping-pong activation (fp16)
__device__ __align__(16) __half g_hh[(size_t)N_NODES * HID];  // ping-pong activation (fp16)
__device__ float g_dinv[N_NODES];
__device__ int   g_deg[N_NODES];
__device__ int   g_off[N_NODES];
__device__ int   g_rank[N_EDGES];                            // per-edge slot within dst node
__device__ int   g_total;
__device__ __align__(8) int2 g_cedge[N_EDGES];               // CSR slot: {src, norm bits}
__device__ __align__(16) float g_pool[N_GRAPHS * HID];

__device__ __forceinline__ void red_add_v4(float* p, float4 v) {
    asm volatile("red.global.add.v4.f32 [%0], {%1,%2,%3,%4};"
                 :: "l"(p), "f"(v.x), "f"(v.y), "f"(v.z), "f"(v.w) : "memory");
}

// ---------------- setup kernels ----------------
__global__ void k_init(int n) {
    int i = blockIdx.x * blockDim.x + threadIdx.x;
    if (i < n) g_deg[i] = 0;
    if (i < N_GRAPHS * HID) g_pool[i] = 0.f;
    if (i == 0) g_total = 0;
}

// degree histogram; atomic return value = edge's rank within its dst node.
// 8 edges/thread for MLP.
__global__ void k_count(const int* __restrict__ dst, int nE) {
    int t = blockIdx.x * blockDim.x + threadIdx.x;
    int e = t << 3;
    if (e + 7 < nE) {
        int4 d0 = __ldg(reinterpret_cast<const int4*>(dst + e));
        int4 d1 = __ldg(reinterpret_cast<const int4*>(dst + e + 4));
        int r0 = atomicAdd(&g_deg[d0.x], 1);
        int r1 = atomicAdd(&g_deg[d0.y], 1);
        int r2 = atomicAdd(&g_deg[d0.z], 1);
        int r3 = atomicAdd(&g_deg[d0.w], 1);
        int r4 = atomicAdd(&g_deg[d1.x], 1);
        int r5 = atomicAdd(&g_deg[d1.y], 1);
        int r6 = atomicAdd(&g_deg[d1.z], 1);
        int r7 = atomicAdd(&g_deg[d1.w], 1);
        *reinterpret_cast<int4*>(&g_rank[e])     = make_int4(r0, r1, r2, r3);
        *reinterpret_cast<int4*>(&g_rank[e + 4]) = make_int4(r4, r5, r6, r7);
    } else {
        for (int i = e; i < nE; i++) g_rank[i] = atomicAdd(&g_deg[__ldg(dst + i)], 1);
    }
}

// single-kernel offset allocation: warp-scan + one atomicAdd per warp.
__global__ void k_scan(int n) {
    int i = blockIdx.x * blockDim.x + threadIdx.x;
    int lane = threadIdx.x & 31;
    int v = (i < n) ? g_deg[i] : 0;
    int incl = v;
    #pragma unroll
    for (int off = 1; off < 32; off <<= 1) {
        int t = __shfl_up_sync(0xffffffff, incl, off);
        if (lane >= off) incl += t;
    }
    int wtot = __shfl_sync(0xffffffff, incl, 31);
    int base = 0;
    if (lane == 31) base = atomicAdd(&g_total, wtot);
    base = __shfl_sync(0xffffffff, base, 31);
    if (i < n) {
        g_off[i] = base + incl - v;
        g_dinv[i] = rsqrtf((float)v + 1.0f);   // +1 self-loop
    }
}

// fill CSR slots ATOMIC-FREE: pos = off[dst] + rank[e]. 8 edges/thread, streaming.
__global__ void k_fill(const int* __restrict__ src, const int* __restrict__ dst, int nE) {
    int t = blockIdx.x * blockDim.x + threadIdx.x;
    int e = t << 3;
    if (e + 7 < nE) {
        int4 s0 = __ldg(reinterpret_cast<const int4*>(src + e));
        int4 s1 = __ldg(reinterpret_cast<const int4*>(src + e + 4));
        int4 d0 = __ldg(reinterpret_cast<const int4*>(dst + e));
        int4 d1 = __ldg(reinterpret_cast<const int4*>(dst + e + 4));
        int4 r0 = *reinterpret_cast<const int4*>(&g_rank[e]);
        int4 r1 = *reinterpret_cast<const int4*>(&g_rank[e + 4]);
        g_cedge[g_off[d0.x] + r0.x] = make_int2(s0.x, __float_as_int(g_dinv[s0.x] * g_dinv[d0.x]));
        g_cedge[g_off[d0.y] + r0.y] = make_int2(s0.y, __float_as_int(g_dinv[s0.y] * g_dinv[d0.y]));
        g_cedge[g_off[d0.z] + r0.z] = make_int2(s0.z, __float_as_int(g_dinv[s0.z] * g_dinv[d0.z]));
        g_cedge[g_off[d0.w] + r0.w] = make_int2(s0.w, __float_as_int(g_dinv[s0.w] * g_dinv[d0.w]));
        g_cedge[g_off[d1.x] + r1.x] = make_int2(s1.x, __float_as_int(g_dinv[s1.x] * g_dinv[d1.x]));
        g_cedge[g_off[d1.y] + r1.y] = make_int2(s1.y, __float_as_int(g_dinv[s1.y] * g_dinv[d1.y]));
        g_cedge[g_off[d1.z] + r1.z] = make_int2(s1.z, __float_as_int(g_dinv[s1.z] * g_dinv[d1.z]));
        g_cedge[g_off[d1.w] + r1.w] = make_int2(s1.w, __float_as_int(g_dinv[s1.w] * g_dinv[d1.w]));
    } else {
        for (int i = e; i < nE; i++) {
            int s = __ldg(src + i), d = __ldg(dst + i);
            g_cedge[g_off[d] + g_rank[i]] = make_int2(s, __float_as_int(g_dinv[s] * g_dinv[d]));
        }
    }
}

// ---------------- layer 1 (fused aggregate + 6->64 gemm + bias + relu) -> fp16 ----------
__global__ void k_layer1(const float* __restrict__ x, const float* __restrict__ W,
                         const float* __restrict__ b, int n) {
    __shared__ float Ws[F_IN][HID];
    __shared__ float bs[HID];
    __shared__ float Xa[32][F_IN + 2];
    int tid = threadIdx.x;
    for (int i = tid; i < F_IN * HID; i += 256) Ws[i >> 6][i & 63] = W[i];
    if (tid < HID) bs[tid] = b[tid];

    int ln = tid >> 3;
    int c = tid & 7;
    int node = blockIdx.x * 32 + ln;
    if (node < n && c < F_IN) {
        float di = g_dinv[node];
        float acc = __ldg(x + (size_t)node * F_IN + c) * di * di;
        int p = g_off[node], e = p + g_deg[node];
        for (; p < e; p++) {
            int2 ed = __ldg(&g_cedge[p]);
            acc = fmaf(__ldg(x + (size_t)ed.x * F_IN + c), __int_as_float(ed.y), acc);
        }
        Xa[ln][c] = acc;
    }
    __syncthreads();

    int base = blockIdx.x * 32;
    #pragma unroll
    for (int j = 0; j < 8; j++) {
        int idx = j * 256 + tid;
        int nl = idx >> 6, col = idx & 63;
        int nd = base + nl;
        if (nd < n) {
            float acc = bs[col];
            #pragma unroll
            for (int k = 0; k < F_IN; k++)
                acc = fmaf(Xa[nl][k], Ws[k][col], acc);
            g_hx[(size_t)nd * HID + col] = __float2half(fmaxf(acc, 0.f));
        }
    }
}

// ---------------- fused layer: out = relu((A_hat @ src) @ W + b), fp16 I/O -------------
template <bool POOL>
__global__ void k_layer64(const __half* __restrict__ src, __half* __restrict__ dst,
                          const float* __restrict__ W, const float* __restrict__ b,
                          const int* __restrict__ batch, int n) {
    __shared__ float4 Ws[HID][HID / 4];      // 16KB  [k][colgroup]
    __shared__ float  XsT[HID][64 + 4];      // 17KB  [k][node_local]
    __shared__ float  bs[HID];
    int tid = threadIdx.x;
    const float4* W4 = reinterpret_cast<const float4*>(W);
    #pragma unroll
    for (int i = tid; i < HID * HID / 4; i += 256)
        Ws[i >> 4][i & 15] = W4[i];
    if (tid < HID) bs[tid] = b[tid];

    int base = blockIdx.x * 64;
    int ln = tid >> 4;            // node lane 0..15
    int lane = tid & 15;          // col-group lane
    int c4 = lane << 2;

    auto load4 = [&](const __half* p, int row) -> float4 {
        uint2 raw = __ldg(reinterpret_cast<const uint2*>(p + (size_t)row * HID + c4));
        __half2 ha = *reinterpret_cast<__half2*>(&raw.x);
        __half2 hb = *reinterpret_cast<__half2*>(&raw.y);
        float2 fa = __half22float2(ha);
        float2 fb = __half22float2(hb);
        return make_float4(fa.x, fa.y, fb.x, fb.y);
    };

    // ---- phase 1: aggregate 64 rows; store transposed into XsT ----
    #pragma unroll
    for (int g = 0; g < 4; g++) {
        int nl = g * 16 + ln;
        int node = base + nl;
        float4 acc = make_float4(0.f, 0.f, 0.f, 0.f);
        if (node < n) {
            float di = g_dinv[node];
            float sl = di * di;
            acc = load4(src, node);
            acc.x *= sl; acc.y *= sl; acc.z *= sl; acc.w *= sl;
            int p = g_off[node], e = p + g_deg[node];
            for (; p + 3 < e; p += 4) {
                int2 e0 = __ldg(&g_cedge[p]);
                int2 e1 = __ldg(&g_cedge[p + 1]);
                int2 e2 = __ldg(&g_cedge[p + 2]);
                int2 e3 = __ldg(&g_cedge[p + 3]);
                float4 v0 = load4(src, e0.x);
                float4 v1 = load4(src, e1.x);
                float4 v2 = load4(src, e2.x);
                float4 v3 = load4(src, e3.x);
                float n0 = __int_as_float(e0.y), n1 = __int_as_float(e1.y);
                float n2 = __int_as_float(e2.y), n3 = __int_as_float(e3.y);
                acc.x = fmaf(v0.x, n0, acc.x); acc.y = fmaf(v0.y, n0, acc.y);
                acc.z = fmaf(v0.z, n0, acc.z); acc.w = fmaf(v0.w, n0, acc.w);
                acc.x = fmaf(v1.x, n1, acc.x); acc.y = fmaf(v1.y, n1, acc.y);
                acc.z = fmaf(v1.z, n1, acc.z); acc.w = fmaf(v1.w, n1, acc.w);
                acc.x = fmaf(v2.x, n2, acc.x); acc.y = fmaf(v2.y, n2, acc.y);
                acc.z = fmaf(v2.z, n2, acc.z); acc.w = fmaf(v2.w, n2, acc.w);
                acc.x = fmaf(v3.x, n3, acc.x); acc.y = fmaf(v3.y, n3, acc.y);
                acc.z = fmaf(v3.z, n3, acc.z); acc.w = fmaf(v3.w, n3, acc.w);
            }
            for (; p < e; p++) {
                int2 e0 = __ldg(&g_cedge[p]);
                float4 v0 = load4(src, e0.x);
                float n0 = __int_as_float(e0.y);
                acc.x = fmaf(v0.x, n0, acc.x); acc.y = fmaf(v0.y, n0, acc.y);
                acc.z = fmaf(v0.z, n0, acc.z); acc.w = fmaf(v0.w, n0, acc.w);
            }
        }
        XsT[c4 + 0][nl] = acc.x;
        XsT[c4 + 1][nl] = acc.y;
        XsT[c4 + 2][nl] = acc.z;
        XsT[c4 + 3][nl] = acc.w;
    }
    __syncthreads();

    // ---- phase 2: 4x4 register tile; Y = relu(X @ W + b) ----
    int ng = tid >> 4;
    float4 bb = make_float4(bs[c4], bs[c4 + 1], bs[c4 + 2], bs[c4 + 3]);
    float4 a0 = bb, a1 = bb, a2 = bb, a3 = bb;
    #pragma unroll
    for (int k = 0; k < HID; k++) {
        float4 xv = *reinterpret_cast<const float4*>(&XsT[k][ng * 4]);
        float4 w  = Ws[k][lane];
        a0.x = fmaf(xv.x, w.x, a0.x); a0.y = fmaf(xv.x, w.y, a0.y);
        a0.z = fmaf(xv.x, w.z, a0.z); a0.w = fmaf(xv.x, w.w, a0.w);
        a1.x = fmaf(xv.y, w.x, a1.x); a1.y = fmaf(xv.y, w.y, a1.y);
        a1.z = fmaf(xv.y, w.z, a1.z); a1.w = fmaf(xv.y, w.w, a1.w);
        a2.x = fmaf(xv.z, w.x, a2.x); a2.y = fmaf(xv.z, w.y, a2.y);
        a2.z = fmaf(xv.z, w.z, a2.z); a2.w = fmaf(xv.z, w.w, a2.w);
        a3.x = fmaf(xv.w, w.x, a3.x); a3.y = fmaf(xv.w, w.y, a3.y);
        a3.z = fmaf(xv.w, w.z, a3.z); a3.w = fmaf(xv.w, w.w, a3.w);
    }
    float4 accs[4] = {a0, a1, a2, a3};
    #pragma unroll
    for (int i = 0; i < 4; i++) {
        int node = base + ng * 4 + i;
        if (node >= n) continue;
        float4 acc = accs[i];
        acc.x = fmaxf(acc.x, 0.f);
        acc.y = fmaxf(acc.y, 0.f);
        acc.z = fmaxf(acc.z, 0.f);
        acc.w = fmaxf(acc.w, 0.f);
        if (POOL) {
            int gr = __ldg(batch + node);
            red_add_v4(g_pool + gr * HID + c4, acc);
        } else {
            __half2 h0 = __floats2half2_rn(acc.x, acc.y);
            __half2 h1 = __floats2half2_rn(acc.z, acc.w);
            uint2 raw;
            raw.x = *reinterpret_cast<uint32_t*>(&h0);
            raw.y = *reinterpret_cast<uint32_t*>(&h1);
            *reinterpret_cast<uint2*>(dst + (size_t)node * HID + c4) = raw;
        }
    }
}

// ---------------- fc (graph sizes via binary search on sorted batch) ----------------
__global__ void k_fc(const float* __restrict__ Wfc, const float* __restrict__ bfc,
                     const int* __restrict__ batch, int n, float* __restrict__ out) {
    __shared__ float m[HID];
    __shared__ float inv_cnt;
    int g = blockIdx.x;
    if (threadIdx.x == 0) {
        int lo = 0, hi = n;
        while (lo < hi) { int mid = (lo + hi) >> 1; if (__ldg(batch + mid) < g) lo = mid + 1; else hi = mid; }
        int start = lo;
        lo = start; hi = n;
        while (lo < hi) { int mid = (lo + hi) >> 1; if (__ldg(batch + mid) < g + 1) lo = mid + 1; else hi = mid; }
        int cnt = lo - start;
        inv_cnt = 1.0f / fmaxf((float)cnt, 1.0f);
    }
    __syncthreads();
    if (threadIdx.x < HID) {
        m[threadIdx.x] = g_pool[g * HID + threadIdx.x] * inv_cnt;
    }
    __syncthreads();
    int col = threadIdx.x;
    float acc = __ldg(bfc + col);
    #pragma unroll
    for (int k = 0; k < HID; k++)
        acc = fmaf(m[k], __ldg(Wfc + k * EMB + col), acc);
    out[g * EMB + col] = fmaxf(acc, 0.f);
}

// ---------------- launch ----------------
extern "C" void kernel_launch(void* const* d_in, const int* in_sizes, int n_in,
                              void* d_out, int out_size) {
    const float* x     = (const float*)d_in[0];
    const int*   ei    = (const int*)d_in[1];
    const int*   batch = (const int*)d_in[2];
    const float* W1 = (const float*)d_in[3];
    const float* b1 = (const float*)d_in[4];
    const float* W2 = (const float*)d_in[5];
    const float* b2 = (const float*)d_in[6];
    const float* W3 = (const float*)d_in[7];
    const float* b3 = (const float*)d_in[8];
    const float* Wfc = (const float*)d_in[9];
    const float* bfc = (const float*)d_in[10];
    float* out = (float*)d_out;

    const int n  = in_sizes[0] / F_IN;
    const int nE = in_sizes[1] / 2;

    const int T = 256;
    const int gN  = (n + T - 1) / T;
    const int gE8 = ((nE + 7) / 8 + T - 1) / T;

    __half *gx_ptr, *gh_ptr;
    cudaGetSymbolAddress((void**)&gx_ptr, g_hx);
    cudaGetSymbolAddress((void**)&gh_ptr, g_hh);

    // setup
    k_init<<<gN, T>>>(n);
    k_count<<<gE8, T>>>(ei + nE, nE);
    k_scan<<<gN, T>>>(n);
    k_fill<<<gE8, T>>>(ei, ei + nE, nE);

    // layer 1 (agg6 + gemm6 fused) -> g_hx (fp16)
    k_layer1<<<(n + 31) / 32, T>>>(x, W1, b1, n);

    // layer 2 (agg + gemm fused) g_hx -> g_hh
    k_layer64<false><<<(n + 63) / 64, T>>>(gx_ptr, gh_ptr, W2, b2, batch, n);

    // layer 3 (agg + gemm + mean-pool fused) g_hh -> g_pool
    k_layer64<true><<<(n + 63) / 64, T>>>(gh_ptr, nullptr, W3, b3, batch, n);

    // fc
    k_fc<<<N_GRAPHS, EMB>>>(Wfc, bfc, batch, n, out);
}